// round 9
// baseline (speedup 1.0000x reference)
#include <cuda_runtime.h>
#include <math.h>

#define BATCH 4
#define HW 16384
#define NCH 64
#define C3 192
#define NHEADS 4
#define HD 16
#define NKEY 100

typedef unsigned long long u64;

__device__ __forceinline__ u64 pack2(float a, float b){
  u64 r; asm("mov.b64 %0, {%1, %2};" : "=l"(r) : "f"(a), "f"(b)); return r;
}
__device__ __forceinline__ void fma2(u64 &d, u64 a, u64 b){
  asm("fma.rn.f32x2 %0, %1, %2, %0;" : "+l"(d) : "l"(a), "l"(b));
}
__device__ __forceinline__ void unpack2(u64 a, float &x, float &y){
  asm("mov.b64 {%0, %1}, %2;" : "=f"(x), "=f"(y) : "l"(a));
}
__device__ __forceinline__ float hadd2(u64 a){
  float x, y; unpack2(a, x, y); return x + y;
}
union F4U { float4 f; ulonglong2 u; };

// ---------------- scratch ----------------
__device__ __align__(16) float g_y1[BATCH*C3*HW];
__device__ __align__(16) float g_qkv[BATCH*C3*HW];
__device__ __align__(16) float g_attn[BATCH*NCH*HW];
__device__ __align__(16) float g_out3[BATCH*NCH*HW];
__device__ float g_Sp[BATCH*128*NCH];
__device__ __align__(16) float g_Gpart[BATCH*128*NCH*NCH];
__device__ __align__(16) float g_Gred[16*BATCH*NCH*NCH];
__device__ float g_S[BATCH*NCH];
__device__ int   g_idx[BATCH*NCH];

// ================= tiled GEMM: fused maxpool2 + conv1x1 (64 -> 192) =================
// block = (b, h): 128 pixels. 256 thr: to=tid>>4 (4 outs), tp=tid&15 (px float4s tp & tp+16)
__global__ __launch_bounds__(256) void k_pool_qkv(const float* __restrict__ x,
                                                  const float* __restrict__ wq){
  __shared__ __align__(16) float sA[64*128];   // 32KB, plain row-major [c][px]
  __shared__ __align__(16) float sW[64*64];    // 16KB, Wt[k][o] for current o-tile
  int tid = threadIdx.x;
  int b = blockIdx.x >> 7, h = blockIdx.x & 127;
  float4* sA4 = (float4*)sA;
#pragma unroll
  for (int it = 0; it < 8; it++){
    int idx = tid + it*256;
    int c = idx >> 5, seg = idx & 31;
    const float* base = x + ((b*64+c)<<16) + (h<<9) + (seg<<3);
    float4 f0 = *(const float4*)base;
    float4 f1 = *(const float4*)(base+4);
    float4 g0 = *(const float4*)(base+256);
    float4 g1 = *(const float4*)(base+260);
    float4 q;
    q.x = fmaxf(fmaxf(f0.x,f0.y), fmaxf(g0.x,g0.y));
    q.y = fmaxf(fmaxf(f0.z,f0.w), fmaxf(g0.z,g0.w));
    q.z = fmaxf(fmaxf(f1.x,f1.y), fmaxf(g1.x,g1.y));
    q.w = fmaxf(fmaxf(f1.z,f1.w), fmaxf(g1.z,g1.w));
    sA4[c*32 + seg] = q;
  }
  int to = tid >> 4, tp = tid & 15;
  const float4* sW4 = (const float4*)sW;
  const F4U* sAu = (const F4U*)sA;
  float* outb = g_y1 + b*C3*HW + h*128 + tp*4;
  for (int ot = 0; ot < 3; ot++){
    __syncthreads();
    for (int i = tid; i < 4096; i += 256){
      int o = i >> 6, k = i & 63;
      sW[k*64 + o] = wq[(ot*64 + o)*64 + k];
    }
    __syncthreads();
    u64 acc[4][4];
#pragma unroll
    for (int i = 0; i < 4; i++)
#pragma unroll
      for (int j = 0; j < 4; j++) acc[i][j] = 0ULL;
#pragma unroll 4
    for (int k = 0; k < 64; k++){
      float4 wv = sW4[k*16 + to];
      u64 w0 = pack2(wv.x,wv.x), w1 = pack2(wv.y,wv.y);
      u64 w2 = pack2(wv.z,wv.z), w3 = pack2(wv.w,wv.w);
      F4U a0 = sAu[k*32 + tp];
      F4U a1 = sAu[k*32 + tp + 16];
      fma2(acc[0][0], w0, a0.u.x); fma2(acc[0][1], w0, a0.u.y);
      fma2(acc[0][2], w0, a1.u.x); fma2(acc[0][3], w0, a1.u.y);
      fma2(acc[1][0], w1, a0.u.x); fma2(acc[1][1], w1, a0.u.y);
      fma2(acc[1][2], w1, a1.u.x); fma2(acc[1][3], w1, a1.u.y);
      fma2(acc[2][0], w2, a0.u.x); fma2(acc[2][1], w2, a0.u.y);
      fma2(acc[2][2], w2, a1.u.x); fma2(acc[2][3], w2, a1.u.y);
      fma2(acc[3][0], w3, a0.u.x); fma2(acc[3][1], w3, a0.u.y);
      fma2(acc[3][2], w3, a1.u.x); fma2(acc[3][3], w3, a1.u.y);
    }
#pragma unroll
    for (int i = 0; i < 4; i++){
      int o = ot*64 + to*4 + i;
      ulonglong2 s0; s0.x = acc[i][0]; s0.y = acc[i][1];
      ulonglong2 s1; s1.x = acc[i][2]; s1.y = acc[i][3];
      *(ulonglong2*)(outb + o*HW) = s0;
      *(ulonglong2*)(outb + o*HW + 64) = s1;
    }
  }
}

// ---------------- depthwise 3x3 zero pad, 4 px/thread ----------------
__global__ __launch_bounds__(256) void k_dw3(const float* __restrict__ wd){
  int t = blockIdx.x*256 + threadIdx.x;
  int base = t*4;
  int w4 = base & 127, h = (base>>7)&127, bc = base>>14;
  int ch = bc % C3;
  const float* src = g_y1 + bc*HW;
  const float* kk = wd + ch*9;
  float o0=0.f,o1=0.f,o2=0.f,o3=0.f;
#pragma unroll
  for (int dy = 0; dy < 3; dy++){
    int ih = h + dy - 1;
    if ((unsigned)ih >= 128u) continue;
    const float* r = src + ih*128 + w4;
    float4 m = *(const float4*)r;
    float lf = (w4 > 0)   ? r[-1] : 0.f;
    float rt = (w4 < 124) ? r[4]  : 0.f;
    float ka = kk[dy*3], kb = kk[dy*3+1], kc = kk[dy*3+2];
    o0 = fmaf(lf,ka,fmaf(m.x,kb,fmaf(m.y,kc,o0)));
    o1 = fmaf(m.x,ka,fmaf(m.y,kb,fmaf(m.z,kc,o1)));
    o2 = fmaf(m.y,ka,fmaf(m.z,kb,fmaf(m.w,kc,o2)));
    o3 = fmaf(m.z,ka,fmaf(m.w,kb,fmaf(rt,kc,o3)));
  }
  *(float4*)(g_qkv + base) = make_float4(o0,o1,o2,o3);
}

// ---------------- Gram partials + per-slice channel sums ----------------
__global__ __launch_bounds__(256) void k_gram(){
  __shared__ __align__(16) float sh[64*128];
  int b = blockIdx.y, sp = blockIdx.x;
  int tid = threadIdx.x;
  int tc = (tid >> 4) << 2;
  int td = (tid & 15) << 2;
  const float* qb = g_qkv + b*C3*HW + sp*128;
  float4* sh4 = (float4*)sh;
  for (int i = tid; i < 2048; i += 256){
    int c = i >> 5, nn4 = i & 31;
    sh4[c*32 + (nn4 ^ (c>>2))] = *(const float4*)(qb + c*HW + nn4*4);
  }
  __syncthreads();
  u64 acc[4][4];
#pragma unroll
  for (int i = 0; i < 4; i++)
#pragma unroll
    for (int j = 0; j < 4; j++) acc[i][j] = 0ULL;
  const F4U* shf = (const F4U*)sh;
  for (int nn4 = 0; nn4 < 32; nn4++){
    F4U av[4], bv[4];
#pragma unroll
    for (int i = 0; i < 4; i++){ int r = tc + i; av[i] = shf[r*32 + (nn4 ^ (r>>2))]; }
#pragma unroll
    for (int j = 0; j < 4; j++){ int r = td + j; bv[j] = shf[r*32 + (nn4 ^ (r>>2))]; }
#pragma unroll
    for (int i = 0; i < 4; i++)
#pragma unroll
      for (int j = 0; j < 4; j++){
        fma2(acc[i][j], av[i].u.x, bv[j].u.x);
        fma2(acc[i][j], av[i].u.y, bv[j].u.y);
      }
  }
#pragma unroll
  for (int i = 0; i < 4; i++)
#pragma unroll
    for (int j = 0; j < 4; j++)
      g_Gpart[((b*128+sp)*64 + tc+i)*64 + td+j] = hadd2(acc[i][j]);
  if (tid < 64){
    float s = 0.f;
    for (int nn4 = 0; nn4 < 32; nn4++){
      F4U f = shf[tid*32 + (nn4 ^ (tid>>2))];
      s += (f.f.x + f.f.y) + (f.f.z + f.f.w);
    }
    g_Sp[(b*128+sp)*64 + tid] = s;
  }
}

// ---------------- chip-wide reduction: 16 chunks of 8 slices ----------------
__global__ __launch_bounds__(256) void k_reduce(){
  int t = blockIdx.x*256 + threadIdx.x;      // 262144 threads
  int entry = t & 16383;
  int chunk = t >> 14;                       // 0..15
  int b = entry >> 12, cd = entry & 4095;
  const float* src = g_Gpart + ((size_t)(b*128 + chunk*8))*4096 + cd;
  float s = 0.f;
#pragma unroll
  for (int sp = 0; sp < 8; sp++) s += src[(size_t)sp*4096];
  g_Gred[(size_t)chunk*16384 + entry] = s;
  if (chunk == 0 && cd < 64){
    const float* sq = g_Sp + b*128*64 + cd;
    float ss = 0.f;
#pragma unroll 8
    for (int sp = 0; sp < 128; sp++) ss += sq[sp*64];
    g_S[b*64 + cd] = ss;
  }
}

// ---------------- cov -> sim -> stable ranking ----------------
__global__ void k_stats(){
  __shared__ float covs[64][64];
  __shared__ float stds[64];
  __shared__ float sims[64];
  __shared__ float shS[64];
  int b = blockIdx.x;
  if (threadIdx.x < 64) shS[threadIdx.x] = g_S[b*64 + threadIdx.x];
  __syncthreads();
  for (int pr = threadIdx.x; pr < 4096; pr += 256){
    int c = pr>>6, d = pr&63;
    float g = 0.f;
#pragma unroll
    for (int ch = 0; ch < 16; ch++) g += g_Gred[(size_t)ch*16384 + b*4096 + pr];
    covs[c][d] = g - shS[c]*shS[d]*(1.0f/16384.0f);
  }
  __syncthreads();
  if (threadIdx.x < 64)
    stds[threadIdx.x] = sqrtf(covs[threadIdx.x][threadIdx.x] + 1e-8f);
  __syncthreads();
  if (threadIdx.x < 64){
    int c = threadIdx.x;
    float sc = stds[c], a = 0.f;
    for (int d = 0; d < 64; d++) a += covs[c][d] / fmaxf(sc*stds[d], 1e-8f);
    sims[c] = a * (1.0f/64.0f);
  }
  __syncthreads();
  if (threadIdx.x < 64){
    int c = threadIdx.x;
    float v = sims[c]; int r = 0;
    for (int d = 0; d < 64; d++){
      float u = sims[d];
      r += (u > v) || (u == v && d < c);
    }
    g_idx[b*64 + r] = c;
  }
}

// ---------------- block-local halo attention, 128 thr, split-K softmax ----------------
__global__ __launch_bounds__(128) void k_attn(const float* __restrict__ gatew,
    const float* __restrict__ gateb, const float* __restrict__ temp,
    const float* __restrict__ relh, const float* __restrict__ relw){
  __shared__ int   sc[HD];
  __shared__ __align__(16) float kn[NKEY][HD];
  __shared__ __align__(16) float vv[NKEY][HD];
  __shared__ __align__(16) float gws[HD*HD];
  __shared__ float gbs[HD];
  __shared__ float sred[64][18];
  int tid = threadIdx.x;
  int g = blockIdx.y, b = blockIdx.z;
  if (tid < HD){
    sc[tid]  = g_idx[b*64 + g*HD + tid];
    gbs[tid] = gateb[g*HD + tid];
  }
  for (int i = tid; i < HD*HD; i += 128) gws[i] = gatew[g*HD*HD + i];
  __syncthreads();
  int bh = blockIdx.x >> 4, bw = blockIdx.x & 15;
  int h0 = bh*8, w0 = bw*8;
  if (tid < NKEY){
    int p = tid;
    int ry = p/10, rx = p - ry*10;
    int gh = h0 - 1 + ry, gw2 = w0 - 1 + rx;
    bool inb = ((unsigned)gh < 128u) && ((unsigned)gw2 < 128u);
    int posk = gh*128 + gw2;
    float ss = 0.f; float tmp[HD];
#pragma unroll
    for (int c = 0; c < HD; c++){
      float base = 0.f, vval = 0.f;
      if (inb){
        int off = (b*C3 + sc[c])*HW + posk;
        base = g_qkv[off + 64*HW];
        vval = g_qkv[off + 128*HW];
      }
      float rel = (c < 8) ? relh[(g*10+ry)*8 + c] : relw[(g*10+rx)*8 + (c-8)];
      float kv = base + rel;
      tmp[c] = kv; ss += kv*kv;
      vv[p][c] = vval;
    }
    float inv = 1.0f / fmaxf(sqrtf(ss), 1e-12f);
#pragma unroll
    for (int c = 0; c < HD; c++) kn[p][c] = tmp[c]*inv;
  }
  int q = tid & 63, half = tid >> 6;
  int qy = q >> 3, qx = q & 7;
  int pos = (h0+qy)*128 + (w0+qx);
  float qraw[HD]; float ss = 0.f;
#pragma unroll
  for (int c = 0; c < HD; c++){
    float v = g_qkv[(b*C3 + sc[c])*HW + pos];
    qraw[c] = v; ss += v*v;
  }
  u64 qr2[8];
#pragma unroll
  for (int c = 0; c < HD; c += 2) qr2[c>>1] = pack2(qraw[c], qraw[c+1]);
  float E  = __expf(temp[g]);
  float qs = E / fmaxf(sqrtf(ss), 1e-12f);
  __syncthreads();
  float s = 0.f;
  u64 acc2[8];
#pragma unroll
  for (int i = 0; i < 8; i++) acc2[i] = 0ULL;
  int k0i = half*50;
#pragma unroll 2
  for (int kp = k0i; kp < k0i + 50; kp++){
    const ulonglong2* kk = (const ulonglong2*)kn[kp];
    ulonglong2 k0 = kk[0], k1 = kk[1], k2 = kk[2], k3 = kk[3];
    u64 da = 0ULL, db = 0ULL;
    fma2(da, qr2[0], k0.x); fma2(db, qr2[1], k0.y);
    fma2(da, qr2[2], k1.x); fma2(db, qr2[3], k1.y);
    fma2(da, qr2[4], k2.x); fma2(db, qr2[5], k2.y);
    fma2(da, qr2[6], k3.x); fma2(db, qr2[7], k3.y);
    float l = (hadd2(da) + hadd2(db)) * qs;
    float pv = __expf(l - E);
    s += pv;
    u64 pv2 = pack2(pv, pv);
    const ulonglong2* vk = (const ulonglong2*)vv[kp];
    ulonglong2 v0 = vk[0], v1 = vk[1], v2 = vk[2], v3 = vk[3];
    fma2(acc2[0], pv2, v0.x); fma2(acc2[1], pv2, v0.y);
    fma2(acc2[2], pv2, v1.x); fma2(acc2[3], pv2, v1.y);
    fma2(acc2[4], pv2, v2.x); fma2(acc2[5], pv2, v2.y);
    fma2(acc2[6], pv2, v3.x); fma2(acc2[7], pv2, v3.y);
  }
  float accv[HD];
#pragma unroll
  for (int i = 0; i < 8; i++) unpack2(acc2[i], accv[2*i], accv[2*i+1]);
  if (half == 1){
    sred[q][0] = s;
#pragma unroll
    for (int i = 0; i < HD; i++) sred[q][1+i] = accv[i];
  }
  __syncthreads();
  if (half == 0){
    s += sred[q][0];
#pragma unroll
    for (int i = 0; i < HD; i++) accv[i] += sred[q][1+i];
    float invs = 1.0f / s;
    const ulonglong2* gw2 = (const ulonglong2*)gws;
#pragma unroll
    for (int o = 0; o < HD; o++){
      u64 a = 0ULL;
#pragma unroll
      for (int cc4 = 0; cc4 < 4; cc4++){
        ulonglong2 w = gw2[o*4 + cc4];
        fma2(a, w.x, qr2[2*cc4]); fma2(a, w.y, qr2[2*cc4+1]);
      }
      float ga = gbs[o] + hadd2(a);
      float sig = 1.0f/(1.0f + __expf(-ga));
      g_attn[(b*NCH + sc[o])*HW + pos] = accv[o]*invs*sig;
    }
  }
}

// ================= fully fused tiled MLP: gate->gelu->down->up(+res)->proj =================
// round-7 mapping: to=tid>>4 (4 outs), tp=tid&15 (px float4s tp & tp+16)
__global__ __launch_bounds__(256) void k_mlp(const float* __restrict__ gw,
    const float* __restrict__ gb, const float* __restrict__ dw,
    const float* __restrict__ db, const float* __restrict__ uw,
    const float* __restrict__ ub, const float* __restrict__ pw){
  __shared__ __align__(16) float sA[64*128];
  __shared__ __align__(16) float sW[64*64];
  int tid = threadIdx.x;
  int b = blockIdx.x >> 7, h = blockIdx.x & 127;
  int pos0 = h*128;
  float4* sA4 = (float4*)sA;
  const F4U* sAu = (const F4U*)sA;
  const float4* sW4 = (const float4*)sW;
  int to = tid >> 4, tp = tid & 15;
  // ---- load mixed = attn_out + q + k ----
#pragma unroll
  for (int it = 0; it < 8; it++){
    int idx = tid + it*256;
    int c = idx >> 5, seg = idx & 31;
    float4 a = ((const float4*)(g_attn + (b*64 + c)*HW + pos0))[seg];
    float4 q = ((const float4*)(g_qkv + (b*192 + c)*HW + pos0))[seg];
    float4 k = ((const float4*)(g_qkv + (b*192 + 64 + c)*HW + pos0))[seg];
    float4 m; m.x=a.x+q.x+k.x; m.y=a.y+q.y+k.y; m.z=a.z+q.z+k.z; m.w=a.w+q.w+k.w;
    sA4[c*32 + seg] = m;
  }
  for (int i = tid; i < 4096; i += 256){
    int o = i >> 6, k = i & 63;
    sW[k*64 + o] = gw[o*64 + k];
  }
  __syncthreads();
  // ---- stage 1: gate (64x64) + gelu*mixed ----
  {
    u64 acc[4][4];
#pragma unroll
    for (int i = 0; i < 4; i++){
      float bv = __ldg(gb + to*4 + i);
      u64 bp = pack2(bv, bv);
#pragma unroll
      for (int j = 0; j < 4; j++) acc[i][j] = bp;
    }
#pragma unroll 4
    for (int k = 0; k < 64; k++){
      float4 wv = sW4[k*16 + to];
      u64 w0 = pack2(wv.x,wv.x), w1 = pack2(wv.y,wv.y);
      u64 w2 = pack2(wv.z,wv.z), w3 = pack2(wv.w,wv.w);
      F4U a0 = sAu[k*32 + tp];
      F4U a1 = sAu[k*32 + tp + 16];
      fma2(acc[0][0], w0, a0.u.x); fma2(acc[0][1], w0, a0.u.y);
      fma2(acc[0][2], w0, a1.u.x); fma2(acc[0][3], w0, a1.u.y);
      fma2(acc[1][0], w1, a0.u.x); fma2(acc[1][1], w1, a0.u.y);
      fma2(acc[1][2], w1, a1.u.x); fma2(acc[1][3], w1, a1.u.y);
      fma2(acc[2][0], w2, a0.u.x); fma2(acc[2][1], w2, a0.u.y);
      fma2(acc[2][2], w2, a1.u.x); fma2(acc[2][3], w2, a1.u.y);
      fma2(acc[3][0], w3, a0.u.x); fma2(acc[3][1], w3, a0.u.y);
      fma2(acc[3][2], w3, a1.u.x); fma2(acc[3][3], w3, a1.u.y);
    }
    __syncthreads();
#pragma unroll
    for (int i = 0; i < 4; i++){
      int o = to*4 + i;
      F4U m0 = sAu[o*32 + tp];
      F4U m1 = sAu[o*32 + tp + 16];
      float v[8];
      unpack2(acc[i][0], v[0], v[1]); unpack2(acc[i][1], v[2], v[3]);
      unpack2(acc[i][2], v[4], v[5]); unpack2(acc[i][3], v[6], v[7]);
      float mm[8];
      mm[0]=m0.f.x; mm[1]=m0.f.y; mm[2]=m0.f.z; mm[3]=m0.f.w;
      mm[4]=m1.f.x; mm[5]=m1.f.y; mm[6]=m1.f.z; mm[7]=m1.f.w;
#pragma unroll
      for (int j = 0; j < 8; j++)
        v[j] = 0.5f*v[j]*(1.0f + erff(v[j]*0.70710678118f)) * mm[j];
      sA4[o*32 + tp]      = make_float4(v[0],v[1],v[2],v[3]);
      sA4[o*32 + tp + 16] = make_float4(v[4],v[5],v[6],v[7]);
    }
  }
  for (int i = tid; i < 2048; i += 256){
    int o = i >> 6, k = i & 63;
    sW[k*32 + o] = dw[o*64 + k];
  }
  __syncthreads();
  // ---- stage 2: down (32x64) ----
  {
    u64 acc[2][4];
#pragma unroll
    for (int i = 0; i < 2; i++){
      float bv = __ldg(db + to*2 + i);
      u64 bp = pack2(bv, bv);
#pragma unroll
      for (int j = 0; j < 4; j++) acc[i][j] = bp;
    }
    const float2* sW2 = (const float2*)sW;
#pragma unroll 4
    for (int k = 0; k < 64; k++){
      float2 wv = sW2[k*16 + to];
      u64 w0 = pack2(wv.x,wv.x), w1 = pack2(wv.y,wv.y);
      F4U a0 = sAu[k*32 + tp];
      F4U a1 = sAu[k*32 + tp + 16];
      fma2(acc[0][0], w0, a0.u.x); fma2(acc[0][1], w0, a0.u.y);
      fma2(acc[0][2], w0, a1.u.x); fma2(acc[0][3], w0, a1.u.y);
      fma2(acc[1][0], w1, a0.u.x); fma2(acc[1][1], w1, a0.u.y);
      fma2(acc[1][2], w1, a1.u.x); fma2(acc[1][3], w1, a1.u.y);
    }
    __syncthreads();
#pragma unroll
    for (int i = 0; i < 2; i++){
      int o = to*2 + i;
      F4U s0, s1;
      s0.u.x = acc[i][0]; s0.u.y = acc[i][1];
      s1.u.x = acc[i][2]; s1.u.y = acc[i][3];
      sA4[o*32 + tp]      = s0.f;
      sA4[o*32 + tp + 16] = s1.f;
    }
  }
  for (int i = tid; i < 2048; i += 256){
    int oo = i & 63; int kk2 = i >> 6;   // kk2 < 32
    sW[kk2*64 + oo] = uw[oo*32 + kk2];
  }
  __syncthreads();
  // ---- stage 3: up (64x32) + attn residual ----
  {
    u64 acc[4][4];
#pragma unroll
    for (int i = 0; i < 4; i++){
      float bv = __ldg(ub + to*4 + i);
      u64 bp = pack2(bv, bv);
#pragma unroll
      for (int j = 0; j < 4; j++) acc[i][j] = bp;
    }
#pragma unroll 4
    for (int k = 0; k < 32; k++){
      float4 wv = sW4[k*16 + to];
      u64 w0 = pack2(wv.x,wv.x), w1 = pack2(wv.y,wv.y);
      u64 w2 = pack2(wv.z,wv.z), w3 = pack2(wv.w,wv.w);
      F4U a0 = sAu[k*32 + tp];
      F4U a1 = sAu[k*32 + tp + 16];
      fma2(acc[0][0], w0, a0.u.x); fma2(acc[0][1], w0, a0.u.y);
      fma2(acc[0][2], w0, a1.u.x); fma2(acc[0][3], w0, a1.u.y);
      fma2(acc[1][0], w1, a0.u.x); fma2(acc[1][1], w1, a0.u.y);
      fma2(acc[1][2], w1, a1.u.x); fma2(acc[1][3], w1, a1.u.y);
      fma2(acc[2][0], w2, a0.u.x); fma2(acc[2][1], w2, a0.u.y);
      fma2(acc[2][2], w2, a1.u.x); fma2(acc[2][3], w2, a1.u.y);
      fma2(acc[3][0], w3, a0.u.x); fma2(acc[3][1], w3, a0.u.y);
      fma2(acc[3][2], w3, a1.u.x); fma2(acc[3][3], w3, a1.u.y);
    }
    __syncthreads();
#pragma unroll
    for (int i = 0; i < 4; i++){
      int o = to*4 + i;
      const float4* ao4 = (const float4*)(g_attn + (b*64 + o)*HW + pos0);
      float4 r0 = ao4[tp], r1 = ao4[tp + 16];
      float v[8];
      unpack2(acc[i][0], v[0], v[1]); unpack2(acc[i][1], v[2], v[3]);
      unpack2(acc[i][2], v[4], v[5]); unpack2(acc[i][3], v[6], v[7]);
      sA4[o*32 + tp]      = make_float4(v[0]+r0.x, v[1]+r0.y, v[2]+r0.z, v[3]+r0.w);
      sA4[o*32 + tp + 16] = make_float4(v[4]+r1.x, v[5]+r1.y, v[6]+r1.z, v[7]+r1.w);
    }
  }
  for (int i = tid; i < 4096; i += 256){
    int o = i >> 6, k = i & 63;
    sW[k*64 + o] = pw[o*64 + k];
  }
  __syncthreads();
  // ---- stage 4: proj (64x64) ----
  {
    u64 acc[4][4];
#pragma unroll
    for (int i = 0; i < 4; i++)
#pragma unroll
      for (int j = 0; j < 4; j++) acc[i][j] = 0ULL;
#pragma unroll 4
    for (int k = 0; k < 64; k++){
      float4 wv = sW4[k*16 + to];
      u64 w0 = pack2(wv.x,wv.x), w1 = pack2(wv.y,wv.y);
      u64 w2 = pack2(wv.z,wv.z), w3 = pack2(wv.w,wv.w);
      F4U a0 = sAu[k*32 + tp];
      F4U a1 = sAu[k*32 + tp + 16];
      fma2(acc[0][0], w0, a0.u.x); fma2(acc[0][1], w0, a0.u.y);
      fma2(acc[0][2], w0, a1.u.x); fma2(acc[0][3], w0, a1.u.y);
      fma2(acc[1][0], w1, a0.u.x); fma2(acc[1][1], w1, a0.u.y);
      fma2(acc[1][2], w1, a1.u.x); fma2(acc[1][3], w1, a1.u.y);
      fma2(acc[2][0], w2, a0.u.x); fma2(acc[2][1], w2, a0.u.y);
      fma2(acc[2][2], w2, a1.u.x); fma2(acc[2][3], w2, a1.u.y);
      fma2(acc[3][0], w3, a0.u.x); fma2(acc[3][1], w3, a0.u.y);
      fma2(acc[3][2], w3, a1.u.x); fma2(acc[3][3], w3, a1.u.y);
    }
    float* outb = g_out3 + b*NCH*HW + pos0 + tp*4;
#pragma unroll
    for (int i = 0; i < 4; i++){
      int o = to*4 + i;
      ulonglong2 s0; s0.x = acc[i][0]; s0.y = acc[i][1];
      ulonglong2 s1; s1.x = acc[i][2]; s1.y = acc[i][3];
      *(ulonglong2*)(outb + o*HW) = s0;
      *(ulonglong2*)(outb + o*HW + 64) = s1;
    }
  }
}

// ============ fused: depthwise 3x3 reflect + bias + bilinear x2 upsample ============
__global__ __launch_bounds__(256) void k_lpup(const float* __restrict__ wl,
                                              const float* __restrict__ bl,
                                              float* __restrict__ outp){
  __shared__ __align__(16) float sout[12*128];
  __shared__ float slp[10*128];
  int bc = blockIdx.x >> 4;
  int yt = blockIdx.x & 15;
  int ch = bc & 63;
  int Y0 = yt*16;
  int rmin = (Y0*127)/255;
  const float* src = g_out3 + bc*HW;
  int tid = threadIdx.x;
  float4* sout4 = (float4*)sout;
  for (int i = tid; i < 384; i += 256){
    int j = i >> 5, seg = i & 31;
    int r = rmin - 1 + j;
    r = (r < 0) ? -r : ((r > 127) ? 254 - r : r);
    sout4[j*32 + seg] = ((const float4*)(src + r*128))[seg];
  }
  float bv = bl[ch];
  float k0=wl[ch*9],k1=wl[ch*9+1],k2=wl[ch*9+2],k3=wl[ch*9+3],k4=wl[ch*9+4],
        k5=wl[ch*9+5],k6=wl[ch*9+6],k7=wl[ch*9+7],k8=wl[ch*9+8];
  __syncthreads();
  for (int i = tid; i < 1280; i += 256){
    int j = i >> 7, w = i & 127;
    int wl_ = (w > 0)   ? w-1 : 1;
    int wr_ = (w < 127) ? w+1 : 126;
    const float* r0 = sout + j*128;
    const float* r1 = r0 + 128;
    const float* r2 = r1 + 128;
    float acc = bv;
    acc = fmaf(r0[wl_],k0,fmaf(r0[w],k1,fmaf(r0[wr_],k2,acc)));
    acc = fmaf(r1[wl_],k3,fmaf(r1[w],k4,fmaf(r1[wr_],k5,acc)));
    acc = fmaf(r2[wl_],k6,fmaf(r2[w],k7,fmaf(r2[wr_],k8,acc)));
    slp[j*128 + w] = acc;
  }
  __syncthreads();
  int row = tid >> 4;
  int Y = Y0 + row;
  float cy = Y * (127.0f/255.0f);
  int y0 = (int)cy; if (y0 > 126) y0 = 126;
  float wy = cy - (float)y0;
  int ly = y0 - rmin;
  const float* t0 = slp + ly*128;
  const float* t1 = t0 + 128;
  float* orow = outp + (size_t)bc*65536 + Y*256 + (tid&15)*16;
#pragma unroll
  for (int v = 0; v < 4; v++){
    float4 res;
#pragma unroll
    for (int i2 = 0; i2 < 4; i2++){
      int X = (tid&15)*16 + v*4 + i2;
      float cx = X * (127.0f/255.0f);
      int x0 = (int)cx; if (x0 > 126) x0 = 126;
      float wx = cx - (float)x0;
      float v00 = t0[x0], v01 = t0[x0+1];
      float v10 = t1[x0], v11 = t1[x0+1];
      float u0 = v00 + (v10 - v00)*wy;
      float u1 = v01 + (v11 - v01)*wy;
      ((float*)&res)[i2] = u0 + (u1 - u0)*wx;
    }
    *(float4*)(orow + v*4) = res;
  }
}

// ---------------- launch ----------------
extern "C" void kernel_launch(void* const* d_in, const int* in_sizes, int n_in,
                              void* d_out, int out_size){
  const float* x     = (const float*)d_in[0];
  const float* qkvw  = (const float*)d_in[1];
  const float* lcew  = (const float*)d_in[2];
  const float* gatew = (const float*)d_in[3];
  const float* gateb = (const float*)d_in[4];
  const float* temp  = (const float*)d_in[5];
  const float* relh  = (const float*)d_in[6];
  const float* relw  = (const float*)d_in[7];
  const float* downw = (const float*)d_in[8];
  const float* downb = (const float*)d_in[9];
  const float* upw   = (const float*)d_in[10];
  const float* upb   = (const float*)d_in[11];
  const float* gatingw = (const float*)d_in[12];
  const float* gatingb = (const float*)d_in[13];
  const float* projw = (const float*)d_in[14];
  const float* lpw   = (const float*)d_in[15];
  const float* lpb   = (const float*)d_in[16];
  float* outp = (float*)d_out;

  k_pool_qkv<<<512, 256>>>(x, qkvw);
  k_dw3<<<(BATCH*C3*HW)/1024, 256>>>(lcew);
  k_gram<<<dim3(128, BATCH), 256>>>();
  k_reduce<<<1024, 256>>>();
  k_stats<<<BATCH, 256>>>();
  k_attn<<<dim3(256, NHEADS, BATCH), 128>>>(gatew, gateb, temp, relh, relw);
  k_mlp<<<512, 256>>>(gatingw, gatingb, downw, downb, upw, upb, projw);
  k_lpup<<<BATCH*NCH*16, 256>>>(lpw, lpb, outp);
}

// round 11
// speedup vs baseline: 1.0111x; 1.0111x over previous
#include <cuda_runtime.h>
#include <math.h>

#define BATCH 4
#define HW 16384
#define NCH 64
#define C3 192
#define NHEADS 4
#define HD 16
#define NKEY 100

typedef unsigned long long u64;

__device__ __forceinline__ u64 pack2(float a, float b){
  u64 r; asm("mov.b64 %0, {%1, %2};" : "=l"(r) : "f"(a), "f"(b)); return r;
}
__device__ __forceinline__ void fma2(u64 &d, u64 a, u64 b){
  asm("fma.rn.f32x2 %0, %1, %2, %0;" : "+l"(d) : "l"(a), "l"(b));
}
__device__ __forceinline__ void unpack2(u64 a, float &x, float &y){
  asm("mov.b64 {%0, %1}, %2;" : "=f"(x), "=f"(y) : "l"(a));
}
__device__ __forceinline__ float hadd2(u64 a){
  float x, y; unpack2(a, x, y); return x + y;
}
union F4U { float4 f; ulonglong2 u; };

// ---------------- scratch ----------------
__device__ __align__(16) float g_y1[BATCH*C3*HW];
__device__ __align__(16) float g_qkv[BATCH*C3*HW];
__device__ __align__(16) float g_attn[BATCH*NCH*HW];
__device__ __align__(16) float g_out3[BATCH*NCH*HW];
__device__ float g_Sp[BATCH*128*NCH];
__device__ __align__(16) float g_Gpart[BATCH*128*NCH*NCH];
__device__ __align__(16) float g_Gred[16*BATCH*NCH*NCH];
__device__ float g_S[BATCH*NCH];
__device__ int   g_idx[BATCH*NCH];

// ================= tiled GEMM: fused maxpool2 + conv1x1 (64 -> 192) =================
// block = (b, h): 128 pixels. 256 thr: to=tid>>4 (4 outs), tp=tid&15 (px float4s tp & tp+16)
__global__ __launch_bounds__(256) void k_pool_qkv(const float* __restrict__ x,
                                                  const float* __restrict__ wq){
  __shared__ __align__(16) float sA[64*128];   // 32KB, plain row-major [c][px]
  __shared__ __align__(16) float sW[64*64];    // 16KB, Wt[k][o] for current o-tile
  int tid = threadIdx.x;
  int b = blockIdx.x >> 7, h = blockIdx.x & 127;
  float4* sA4 = (float4*)sA;
#pragma unroll
  for (int it = 0; it < 8; it++){
    int idx = tid + it*256;
    int c = idx >> 5, seg = idx & 31;
    const float* base = x + ((b*64+c)<<16) + (h<<9) + (seg<<3);
    float4 f0 = *(const float4*)base;
    float4 f1 = *(const float4*)(base+4);
    float4 g0 = *(const float4*)(base+256);
    float4 g1 = *(const float4*)(base+260);
    float4 q;
    q.x = fmaxf(fmaxf(f0.x,f0.y), fmaxf(g0.x,g0.y));
    q.y = fmaxf(fmaxf(f0.z,f0.w), fmaxf(g0.z,g0.w));
    q.z = fmaxf(fmaxf(f1.x,f1.y), fmaxf(g1.x,g1.y));
    q.w = fmaxf(fmaxf(f1.z,f1.w), fmaxf(g1.z,g1.w));
    sA4[c*32 + seg] = q;
  }
  int to = tid >> 4, tp = tid & 15;
  const float4* sW4 = (const float4*)sW;
  const F4U* sAu = (const F4U*)sA;
  float* outb = g_y1 + b*C3*HW + h*128 + tp*4;
  for (int ot = 0; ot < 3; ot++){
    __syncthreads();
    for (int i = tid; i < 4096; i += 256){
      int o = i >> 6, k = i & 63;
      sW[k*64 + o] = wq[(ot*64 + o)*64 + k];
    }
    __syncthreads();
    u64 acc[4][4];
#pragma unroll
    for (int i = 0; i < 4; i++)
#pragma unroll
      for (int j = 0; j < 4; j++) acc[i][j] = 0ULL;
#pragma unroll 4
    for (int k = 0; k < 64; k++){
      float4 wv = sW4[k*16 + to];
      u64 w0 = pack2(wv.x,wv.x), w1 = pack2(wv.y,wv.y);
      u64 w2 = pack2(wv.z,wv.z), w3 = pack2(wv.w,wv.w);
      F4U a0 = sAu[k*32 + tp];
      F4U a1 = sAu[k*32 + tp + 16];
      fma2(acc[0][0], w0, a0.u.x); fma2(acc[0][1], w0, a0.u.y);
      fma2(acc[0][2], w0, a1.u.x); fma2(acc[0][3], w0, a1.u.y);
      fma2(acc[1][0], w1, a0.u.x); fma2(acc[1][1], w1, a0.u.y);
      fma2(acc[1][2], w1, a1.u.x); fma2(acc[1][3], w1, a1.u.y);
      fma2(acc[2][0], w2, a0.u.x); fma2(acc[2][1], w2, a0.u.y);
      fma2(acc[2][2], w2, a1.u.x); fma2(acc[2][3], w2, a1.u.y);
      fma2(acc[3][0], w3, a0.u.x); fma2(acc[3][1], w3, a0.u.y);
      fma2(acc[3][2], w3, a1.u.x); fma2(acc[3][3], w3, a1.u.y);
    }
#pragma unroll
    for (int i = 0; i < 4; i++){
      int o = ot*64 + to*4 + i;
      ulonglong2 s0; s0.x = acc[i][0]; s0.y = acc[i][1];
      ulonglong2 s1; s1.x = acc[i][2]; s1.y = acc[i][3];
      *(ulonglong2*)(outb + o*HW) = s0;
      *(ulonglong2*)(outb + o*HW + 64) = s1;
    }
  }
}

// ---------------- depthwise 3x3 zero pad, 4 px/thread ----------------
__global__ __launch_bounds__(256) void k_dw3(const float* __restrict__ wd){
  int t = blockIdx.x*256 + threadIdx.x;
  int base = t*4;
  int w4 = base & 127, h = (base>>7)&127, bc = base>>14;
  int ch = bc % C3;
  const float* src = g_y1 + bc*HW;
  const float* kk = wd + ch*9;
  float o0=0.f,o1=0.f,o2=0.f,o3=0.f;
#pragma unroll
  for (int dy = 0; dy < 3; dy++){
    int ih = h + dy - 1;
    if ((unsigned)ih >= 128u) continue;
    const float* r = src + ih*128 + w4;
    float4 m = *(const float4*)r;
    float lf = (w4 > 0)   ? r[-1] : 0.f;
    float rt = (w4 < 124) ? r[4]  : 0.f;
    float ka = kk[dy*3], kb = kk[dy*3+1], kc = kk[dy*3+2];
    o0 = fmaf(lf,ka,fmaf(m.x,kb,fmaf(m.y,kc,o0)));
    o1 = fmaf(m.x,ka,fmaf(m.y,kb,fmaf(m.z,kc,o1)));
    o2 = fmaf(m.y,ka,fmaf(m.z,kb,fmaf(m.w,kc,o2)));
    o3 = fmaf(m.z,ka,fmaf(m.w,kb,fmaf(rt,kc,o3)));
  }
  *(float4*)(g_qkv + base) = make_float4(o0,o1,o2,o3);
}

// ---------------- Gram partials + per-slice channel sums ----------------
__global__ __launch_bounds__(256) void k_gram(){
  __shared__ __align__(16) float sh[64*128];
  int b = blockIdx.y, sp = blockIdx.x;
  int tid = threadIdx.x;
  int tc = (tid >> 4) << 2;
  int td = (tid & 15) << 2;
  const float* qb = g_qkv + b*C3*HW + sp*128;
  float4* sh4 = (float4*)sh;
  for (int i = tid; i < 2048; i += 256){
    int c = i >> 5, nn4 = i & 31;
    sh4[c*32 + (nn4 ^ (c>>2))] = *(const float4*)(qb + c*HW + nn4*4);
  }
  __syncthreads();
  u64 acc[4][4];
#pragma unroll
  for (int i = 0; i < 4; i++)
#pragma unroll
    for (int j = 0; j < 4; j++) acc[i][j] = 0ULL;
  const F4U* shf = (const F4U*)sh;
  for (int nn4 = 0; nn4 < 32; nn4++){
    F4U av[4], bv[4];
#pragma unroll
    for (int i = 0; i < 4; i++){ int r = tc + i; av[i] = shf[r*32 + (nn4 ^ (r>>2))]; }
#pragma unroll
    for (int j = 0; j < 4; j++){ int r = td + j; bv[j] = shf[r*32 + (nn4 ^ (r>>2))]; }
#pragma unroll
    for (int i = 0; i < 4; i++)
#pragma unroll
      for (int j = 0; j < 4; j++){
        fma2(acc[i][j], av[i].u.x, bv[j].u.x);
        fma2(acc[i][j], av[i].u.y, bv[j].u.y);
      }
  }
#pragma unroll
  for (int i = 0; i < 4; i++)
#pragma unroll
    for (int j = 0; j < 4; j++)
      g_Gpart[((b*128+sp)*64 + tc+i)*64 + td+j] = hadd2(acc[i][j]);
  if (tid < 64){
    float s = 0.f;
    for (int nn4 = 0; nn4 < 32; nn4++){
      F4U f = shf[tid*32 + (nn4 ^ (tid>>2))];
      s += (f.f.x + f.f.y) + (f.f.z + f.f.w);
    }
    g_Sp[(b*128+sp)*64 + tid] = s;
  }
}

// ---------------- chip-wide reduction: 16 chunks of 8 slices ----------------
__global__ __launch_bounds__(256) void k_reduce(){
  int t = blockIdx.x*256 + threadIdx.x;      // 262144 threads
  int entry = t & 16383;
  int chunk = t >> 14;                       // 0..15
  int b = entry >> 12, cd = entry & 4095;
  const float* src = g_Gpart + ((size_t)(b*128 + chunk*8))*4096 + cd;
  float s = 0.f;
#pragma unroll
  for (int sp = 0; sp < 8; sp++) s += src[(size_t)sp*4096];
  g_Gred[(size_t)chunk*16384 + entry] = s;
  if (chunk == 0 && cd < 64){
    const float* sq = g_Sp + b*128*64 + cd;
    float ss = 0.f;
#pragma unroll 8
    for (int sp = 0; sp < 128; sp++) ss += sq[sp*64];
    g_S[b*64 + cd] = ss;
  }
}

// ---------------- cov -> sim -> stable ranking ----------------
__global__ void k_stats(){
  __shared__ float covs[64][64];
  __shared__ float stds[64];
  __shared__ float sims[64];
  __shared__ float shS[64];
  int b = blockIdx.x;
  if (threadIdx.x < 64) shS[threadIdx.x] = g_S[b*64 + threadIdx.x];
  __syncthreads();
  for (int pr = threadIdx.x; pr < 4096; pr += 256){
    int c = pr>>6, d = pr&63;
    float g = 0.f;
#pragma unroll
    for (int ch = 0; ch < 16; ch++) g += g_Gred[(size_t)ch*16384 + b*4096 + pr];
    covs[c][d] = g - shS[c]*shS[d]*(1.0f/16384.0f);
  }
  __syncthreads();
  if (threadIdx.x < 64)
    stds[threadIdx.x] = sqrtf(covs[threadIdx.x][threadIdx.x] + 1e-8f);
  __syncthreads();
  if (threadIdx.x < 64){
    int c = threadIdx.x;
    float sc = stds[c], a = 0.f;
    for (int d = 0; d < 64; d++) a += covs[c][d] / fmaxf(sc*stds[d], 1e-8f);
    sims[c] = a * (1.0f/64.0f);
  }
  __syncthreads();
  if (threadIdx.x < 64){
    int c = threadIdx.x;
    float v = sims[c]; int r = 0;
    for (int d = 0; d < 64; d++){
      float u = sims[d];
      r += (u > v) || (u == v && d < c);
    }
    g_idx[b*64 + r] = c;
  }
}

// ---------------- block-local halo attention + gate + scatter (64 thr, round-7) ----------------
__global__ __launch_bounds__(64) void k_attn(const float* __restrict__ gatew,
    const float* __restrict__ gateb, const float* __restrict__ temp,
    const float* __restrict__ relh, const float* __restrict__ relw){
  __shared__ int   sc[HD];
  __shared__ __align__(16) float kn[NKEY][HD];
  __shared__ __align__(16) float vv[NKEY][HD];
  __shared__ __align__(16) float gws[HD*HD];
  __shared__ float gbs[HD];
  int tid = threadIdx.x;
  int g = blockIdx.y, b = blockIdx.z;
  if (tid < HD){
    sc[tid]  = g_idx[b*64 + g*HD + tid];
    gbs[tid] = gateb[g*HD + tid];
  }
  for (int i = tid; i < HD*HD; i += 64) gws[i] = gatew[g*HD*HD + i];
  __syncthreads();
  int bh = blockIdx.x >> 4, bw = blockIdx.x & 15;
  int h0 = bh*8, w0 = bw*8;
  for (int p = tid; p < NKEY; p += 64){
    int ry = p/10, rx = p - ry*10;
    int gh = h0 - 1 + ry, gw2 = w0 - 1 + rx;
    bool inb = ((unsigned)gh < 128u) && ((unsigned)gw2 < 128u);
    int posk = gh*128 + gw2;
    float ss = 0.f; float tmp[HD];
#pragma unroll
    for (int c = 0; c < HD; c++){
      float base = 0.f, vval = 0.f;
      if (inb){
        int off = (b*C3 + sc[c])*HW + posk;
        base = g_qkv[off + 64*HW];
        vval = g_qkv[off + 128*HW];
      }
      float rel = (c < 8) ? relh[(g*10+ry)*8 + c] : relw[(g*10+rx)*8 + (c-8)];
      float kv = base + rel;
      tmp[c] = kv; ss += kv*kv;
      vv[p][c] = vval;
    }
    float inv = 1.0f / fmaxf(sqrtf(ss), 1e-12f);
#pragma unroll
    for (int c = 0; c < HD; c++) kn[p][c] = tmp[c]*inv;
  }
  int qy = tid >> 3, qx = tid & 7;
  int pos = (h0+qy)*128 + (w0+qx);
  float qraw[HD]; float ss = 0.f;
#pragma unroll
  for (int c = 0; c < HD; c++){
    float v = g_qkv[(b*C3 + sc[c])*HW + pos];
    qraw[c] = v; ss += v*v;
  }
  u64 qr2[8];
#pragma unroll
  for (int c = 0; c < HD; c += 2) qr2[c>>1] = pack2(qraw[c], qraw[c+1]);
  float E  = __expf(temp[g]);
  float qs = E / fmaxf(sqrtf(ss), 1e-12f);
  __syncthreads();
  float s = 0.f;
  u64 acc2[8];
#pragma unroll
  for (int i = 0; i < 8; i++) acc2[i] = 0ULL;
#pragma unroll 2
  for (int kp = 0; kp < NKEY; kp++){
    const ulonglong2* kk = (const ulonglong2*)kn[kp];
    ulonglong2 k0 = kk[0], k1 = kk[1], k2 = kk[2], k3 = kk[3];
    u64 da = 0ULL, db = 0ULL;
    fma2(da, qr2[0], k0.x); fma2(db, qr2[1], k0.y);
    fma2(da, qr2[2], k1.x); fma2(db, qr2[3], k1.y);
    fma2(da, qr2[4], k2.x); fma2(db, qr2[5], k2.y);
    fma2(da, qr2[6], k3.x); fma2(db, qr2[7], k3.y);
    float l = (hadd2(da) + hadd2(db)) * qs;
    float pv = __expf(l - E);
    s += pv;
    u64 pv2 = pack2(pv, pv);
    const ulonglong2* vk = (const ulonglong2*)vv[kp];
    ulonglong2 v0 = vk[0], v1 = vk[1], v2 = vk[2], v3 = vk[3];
    fma2(acc2[0], pv2, v0.x); fma2(acc2[1], pv2, v0.y);
    fma2(acc2[2], pv2, v1.x); fma2(acc2[3], pv2, v1.y);
    fma2(acc2[4], pv2, v2.x); fma2(acc2[5], pv2, v2.y);
    fma2(acc2[6], pv2, v3.x); fma2(acc2[7], pv2, v3.y);
  }
  float invs = 1.0f / s;
  float accv[HD];
#pragma unroll
  for (int i = 0; i < 8; i++) unpack2(acc2[i], accv[2*i], accv[2*i+1]);
  const ulonglong2* gw2 = (const ulonglong2*)gws;
#pragma unroll
  for (int o = 0; o < HD; o++){
    u64 a = 0ULL;
#pragma unroll
    for (int cc4 = 0; cc4 < 4; cc4++){
      ulonglong2 w = gw2[o*4 + cc4];
      fma2(a, w.x, qr2[2*cc4]); fma2(a, w.y, qr2[2*cc4+1]);
    }
    float ga = gbs[o] + hadd2(a);
    float sig = 1.0f/(1.0f + __expf(-ga));
    g_attn[(b*NCH + sc[o])*HW + pos] = accv[o]*invs*sig;
  }
}

// ================= fully fused tiled MLP: gate->gelu->down->up(+res)->proj =================
// round-7 mapping: to=tid>>4 (4 outs), tp=tid&15 (px float4s tp & tp+16)
__global__ __launch_bounds__(256) void k_mlp(const float* __restrict__ gw,
    const float* __restrict__ gb, const float* __restrict__ dw,
    const float* __restrict__ db, const float* __restrict__ uw,
    const float* __restrict__ ub, const float* __restrict__ pw){
  __shared__ __align__(16) float sA[64*128];
  __shared__ __align__(16) float sW[64*64];
  int tid = threadIdx.x;
  int b = blockIdx.x >> 7, h = blockIdx.x & 127;
  int pos0 = h*128;
  float4* sA4 = (float4*)sA;
  const F4U* sAu = (const F4U*)sA;
  const float4* sW4 = (const float4*)sW;
  int to = tid >> 4, tp = tid & 15;
  // ---- load mixed = attn_out + q + k ----
#pragma unroll
  for (int it = 0; it < 8; it++){
    int idx = tid + it*256;
    int c = idx >> 5, seg = idx & 31;
    float4 a = ((const float4*)(g_attn + (b*64 + c)*HW + pos0))[seg];
    float4 q = ((const float4*)(g_qkv + (b*192 + c)*HW + pos0))[seg];
    float4 k = ((const float4*)(g_qkv + (b*192 + 64 + c)*HW + pos0))[seg];
    float4 m; m.x=a.x+q.x+k.x; m.y=a.y+q.y+k.y; m.z=a.z+q.z+k.z; m.w=a.w+q.w+k.w;
    sA4[c*32 + seg] = m;
  }
  for (int i = tid; i < 4096; i += 256){
    int o = i >> 6, k = i & 63;
    sW[k*64 + o] = gw[o*64 + k];
  }
  __syncthreads();
  // ---- stage 1: gate (64x64) + gelu*mixed ----
  {
    u64 acc[4][4];
#pragma unroll
    for (int i = 0; i < 4; i++){
      float bv = __ldg(gb + to*4 + i);
      u64 bp = pack2(bv, bv);
#pragma unroll
      for (int j = 0; j < 4; j++) acc[i][j] = bp;
    }
#pragma unroll 4
    for (int k = 0; k < 64; k++){
      float4 wv = sW4[k*16 + to];
      u64 w0 = pack2(wv.x,wv.x), w1 = pack2(wv.y,wv.y);
      u64 w2 = pack2(wv.z,wv.z), w3 = pack2(wv.w,wv.w);
      F4U a0 = sAu[k*32 + tp];
      F4U a1 = sAu[k*32 + tp + 16];
      fma2(acc[0][0], w0, a0.u.x); fma2(acc[0][1], w0, a0.u.y);
      fma2(acc[0][2], w0, a1.u.x); fma2(acc[0][3], w0, a1.u.y);
      fma2(acc[1][0], w1, a0.u.x); fma2(acc[1][1], w1, a0.u.y);
      fma2(acc[1][2], w1, a1.u.x); fma2(acc[1][3], w1, a1.u.y);
      fma2(acc[2][0], w2, a0.u.x); fma2(acc[2][1], w2, a0.u.y);
      fma2(acc[2][2], w2, a1.u.x); fma2(acc[2][3], w2, a1.u.y);
      fma2(acc[3][0], w3, a0.u.x); fma2(acc[3][1], w3, a0.u.y);
      fma2(acc[3][2], w3, a1.u.x); fma2(acc[3][3], w3, a1.u.y);
    }
    __syncthreads();
#pragma unroll
    for (int i = 0; i < 4; i++){
      int o = to*4 + i;
      F4U m0 = sAu[o*32 + tp];
      F4U m1 = sAu[o*32 + tp + 16];
      float v[8];
      unpack2(acc[i][0], v[0], v[1]); unpack2(acc[i][1], v[2], v[3]);
      unpack2(acc[i][2], v[4], v[5]); unpack2(acc[i][3], v[6], v[7]);
      float mm[8];
      mm[0]=m0.f.x; mm[1]=m0.f.y; mm[2]=m0.f.z; mm[3]=m0.f.w;
      mm[4]=m1.f.x; mm[5]=m1.f.y; mm[6]=m1.f.z; mm[7]=m1.f.w;
#pragma unroll
      for (int j = 0; j < 8; j++)
        v[j] = 0.5f*v[j]*(1.0f + erff(v[j]*0.70710678118f)) * mm[j];
      sA4[o*32 + tp]      = make_float4(v[0],v[1],v[2],v[3]);
      sA4[o*32 + tp + 16] = make_float4(v[4],v[5],v[6],v[7]);
    }
  }
  for (int i = tid; i < 2048; i += 256){
    int o = i >> 6, k = i & 63;
    sW[k*32 + o] = dw[o*64 + k];
  }
  __syncthreads();
  // ---- stage 2: down (32x64) ----
  {
    u64 acc[2][4];
#pragma unroll
    for (int i = 0; i < 2; i++){
      float bv = __ldg(db + to*2 + i);
      u64 bp = pack2(bv, bv);
#pragma unroll
      for (int j = 0; j < 4; j++) acc[i][j] = bp;
    }
    const float2* sW2 = (const float2*)sW;
#pragma unroll 4
    for (int k = 0; k < 64; k++){
      float2 wv = sW2[k*16 + to];
      u64 w0 = pack2(wv.x,wv.x), w1 = pack2(wv.y,wv.y);
      F4U a0 = sAu[k*32 + tp];
      F4U a1 = sAu[k*32 + tp + 16];
      fma2(acc[0][0], w0, a0.u.x); fma2(acc[0][1], w0, a0.u.y);
      fma2(acc[0][2], w0, a1.u.x); fma2(acc[0][3], w0, a1.u.y);
      fma2(acc[1][0], w1, a0.u.x); fma2(acc[1][1], w1, a0.u.y);
      fma2(acc[1][2], w1, a1.u.x); fma2(acc[1][3], w1, a1.u.y);
    }
    __syncthreads();
#pragma unroll
    for (int i = 0; i < 2; i++){
      int o = to*2 + i;
      F4U s0, s1;
      s0.u.x = acc[i][0]; s0.u.y = acc[i][1];
      s1.u.x = acc[i][2]; s1.u.y = acc[i][3];
      sA4[o*32 + tp]      = s0.f;
      sA4[o*32 + tp + 16] = s1.f;
    }
  }
  for (int i = tid; i < 2048; i += 256){
    int oo = i & 63; int kk2 = i >> 6;   // kk2 < 32
    sW[kk2*64 + oo] = uw[oo*32 + kk2];
  }
  __syncthreads();
  // ---- stage 3: up (64x32) + attn residual ----
  {
    u64 acc[4][4];
#pragma unroll
    for (int i = 0; i < 4; i++){
      float bv = __ldg(ub + to*4 + i);
      u64 bp = pack2(bv, bv);
#pragma unroll
      for (int j = 0; j < 4; j++) acc[i][j] = bp;
    }
#pragma unroll 4
    for (int k = 0; k < 32; k++){
      float4 wv = sW4[k*16 + to];
      u64 w0 = pack2(wv.x,wv.x), w1 = pack2(wv.y,wv.y);
      u64 w2 = pack2(wv.z,wv.z), w3 = pack2(wv.w,wv.w);
      F4U a0 = sAu[k*32 + tp];
      F4U a1 = sAu[k*32 + tp + 16];
      fma2(acc[0][0], w0, a0.u.x); fma2(acc[0][1], w0, a0.u.y);
      fma2(acc[0][2], w0, a1.u.x); fma2(acc[0][3], w0, a1.u.y);
      fma2(acc[1][0], w1, a0.u.x); fma2(acc[1][1], w1, a0.u.y);
      fma2(acc[1][2], w1, a1.u.x); fma2(acc[1][3], w1, a1.u.y);
      fma2(acc[2][0], w2, a0.u.x); fma2(acc[2][1], w2, a0.u.y);
      fma2(acc[2][2], w2, a1.u.x); fma2(acc[2][3], w2, a1.u.y);
      fma2(acc[3][0], w3, a0.u.x); fma2(acc[3][1], w3, a0.u.y);
      fma2(acc[3][2], w3, a1.u.x); fma2(acc[3][3], w3, a1.u.y);
    }
    __syncthreads();
#pragma unroll
    for (int i = 0; i < 4; i++){
      int o = to*4 + i;
      const float4* ao4 = (const float4*)(g_attn + (b*64 + o)*HW + pos0);
      float4 r0 = ao4[tp], r1 = ao4[tp + 16];
      float v[8];
      unpack2(acc[i][0], v[0], v[1]); unpack2(acc[i][1], v[2], v[3]);
      unpack2(acc[i][2], v[4], v[5]); unpack2(acc[i][3], v[6], v[7]);
      sA4[o*32 + tp]      = make_float4(v[0]+r0.x, v[1]+r0.y, v[2]+r0.z, v[3]+r0.w);
      sA4[o*32 + tp + 16] = make_float4(v[4]+r1.x, v[5]+r1.y, v[6]+r1.z, v[7]+r1.w);
    }
  }
  for (int i = tid; i < 4096; i += 256){
    int o = i >> 6, k = i & 63;
    sW[k*64 + o] = pw[o*64 + k];
  }
  __syncthreads();
  // ---- stage 4: proj (64x64) ----
  {
    u64 acc[4][4];
#pragma unroll
    for (int i = 0; i < 4; i++)
#pragma unroll
      for (int j = 0; j < 4; j++) acc[i][j] = 0ULL;
#pragma unroll 4
    for (int k = 0; k < 64; k++){
      float4 wv = sW4[k*16 + to];
      u64 w0 = pack2(wv.x,wv.x), w1 = pack2(wv.y,wv.y);
      u64 w2 = pack2(wv.z,wv.z), w3 = pack2(wv.w,wv.w);
      F4U a0 = sAu[k*32 + tp];
      F4U a1 = sAu[k*32 + tp + 16];
      fma2(acc[0][0], w0, a0.u.x); fma2(acc[0][1], w0, a0.u.y);
      fma2(acc[0][2], w0, a1.u.x); fma2(acc[0][3], w0, a1.u.y);
      fma2(acc[1][0], w1, a0.u.x); fma2(acc[1][1], w1, a0.u.y);
      fma2(acc[1][2], w1, a1.u.x); fma2(acc[1][3], w1, a1.u.y);
      fma2(acc[2][0], w2, a0.u.x); fma2(acc[2][1], w2, a0.u.y);
      fma2(acc[2][2], w2, a1.u.x); fma2(acc[2][3], w2, a1.u.y);
      fma2(acc[3][0], w3, a0.u.x); fma2(acc[3][1], w3, a0.u.y);
      fma2(acc[3][2], w3, a1.u.x); fma2(acc[3][3], w3, a1.u.y);
    }
    float* outb = g_out3 + b*NCH*HW + pos0 + tp*4;
#pragma unroll
    for (int i = 0; i < 4; i++){
      int o = to*4 + i;
      ulonglong2 s0; s0.x = acc[i][0]; s0.y = acc[i][1];
      ulonglong2 s1; s1.x = acc[i][2]; s1.y = acc[i][3];
      *(ulonglong2*)(outb + o*HW) = s0;
      *(ulonglong2*)(outb + o*HW + 64) = s1;
    }
  }
}

// ============ fused: depthwise 3x3 reflect + bias + bilinear x2 upsample ============
__global__ __launch_bounds__(256) void k_lpup(const float* __restrict__ wl,
                                              const float* __restrict__ bl,
                                              float* __restrict__ outp){
  __shared__ __align__(16) float sout[12*128];
  __shared__ float slp[10*128];
  int bc = blockIdx.x >> 4;
  int yt = blockIdx.x & 15;
  int ch = bc & 63;
  int Y0 = yt*16;
  int rmin = (Y0*127)/255;
  const float* src = g_out3 + bc*HW;
  int tid = threadIdx.x;
  float4* sout4 = (float4*)sout;
  for (int i = tid; i < 384; i += 256){
    int j = i >> 5, seg = i & 31;
    int r = rmin - 1 + j;
    r = (r < 0) ? -r : ((r > 127) ? 254 - r : r);
    sout4[j*32 + seg] = ((const float4*)(src + r*128))[seg];
  }
  float bv = bl[ch];
  float k0=wl[ch*9],k1=wl[ch*9+1],k2=wl[ch*9+2],k3=wl[ch*9+3],k4=wl[ch*9+4],
        k5=wl[ch*9+5],k6=wl[ch*9+6],k7=wl[ch*9+7],k8=wl[ch*9+8];
  __syncthreads();
  for (int i = tid; i < 1280; i += 256){
    int j = i >> 7, w = i & 127;
    int wl_ = (w > 0)   ? w-1 : 1;
    int wr_ = (w < 127) ? w+1 : 126;
    const float* r0 = sout + j*128;
    const float* r1 = r0 + 128;
    const float* r2 = r1 + 128;
    float acc = bv;
    acc = fmaf(r0[wl_],k0,fmaf(r0[w],k1,fmaf(r0[wr_],k2,acc)));
    acc = fmaf(r1[wl_],k3,fmaf(r1[w],k4,fmaf(r1[wr_],k5,acc)));
    acc = fmaf(r2[wl_],k6,fmaf(r2[w],k7,fmaf(r2[wr_],k8,acc)));
    slp[j*128 + w] = acc;
  }
  __syncthreads();
  int row = tid >> 4;
  int Y = Y0 + row;
  float cy = Y * (127.0f/255.0f);
  int y0 = (int)cy; if (y0 > 126) y0 = 126;
  float wy = cy - (float)y0;
  int ly = y0 - rmin;
  const float* t0 = slp + ly*128;
  const float* t1 = t0 + 128;
  float* orow = outp + (size_t)bc*65536 + Y*256 + (tid&15)*16;
#pragma unroll
  for (int v = 0; v < 4; v++){
    float4 res;
#pragma unroll
    for (int i2 = 0; i2 < 4; i2++){
      int X = (tid&15)*16 + v*4 + i2;
      float cx = X * (127.0f/255.0f);
      int x0 = (int)cx; if (x0 > 126) x0 = 126;
      float wx = cx - (float)x0;
      float v00 = t0[x0], v01 = t0[x0+1];
      float v10 = t1[x0], v11 = t1[x0+1];
      float u0 = v00 + (v10 - v00)*wy;
      float u1 = v01 + (v11 - v01)*wy;
      ((float*)&res)[i2] = u0 + (u1 - u0)*wx;
    }
    *(float4*)(orow + v*4) = res;
  }
}

// ---------------- launch ----------------
extern "C" void kernel_launch(void* const* d_in, const int* in_sizes, int n_in,
                              void* d_out, int out_size){
  const float* x     = (const float*)d_in[0];
  const float* qkvw  = (const float*)d_in[1];
  const float* lcew  = (const float*)d_in[2];
  const float* gatew = (const float*)d_in[3];
  const float* gateb = (const float*)d_in[4];
  const float* temp  = (const float*)d_in[5];
  const float* relh  = (const float*)d_in[6];
  const float* relw  = (const float*)d_in[7];
  const float* downw = (const float*)d_in[8];
  const float* downb = (const float*)d_in[9];
  const float* upw   = (const float*)d_in[10];
  const float* upb   = (const float*)d_in[11];
  const float* gatingw = (const float*)d_in[12];
  const float* gatingb = (const float*)d_in[13];
  const float* projw = (const float*)d_in[14];
  const float* lpw   = (const float*)d_in[15];
  const float* lpb   = (const float*)d_in[16];
  float* outp = (float*)d_out;

  k_pool_qkv<<<512, 256>>>(x, qkvw);
  k_dw3<<<(BATCH*C3*HW)/1024, 256>>>(lcew);
  k_gram<<<dim3(128, BATCH), 256>>>();
  k_reduce<<<1024, 256>>>();
  k_stats<<<BATCH, 256>>>();
  k_attn<<<dim3(256, NHEADS, BATCH), 64>>>(gatew, gateb, temp, relh, relw);
  k_mlp<<<512, 256>>>(gatingw, gatingb, downw, downb, upw, upb, projw);
  k_lpup<<<BATCH*NCH*16, 256>>>(lpw, lpb, outp);
}

// round 12
// speedup vs baseline: 1.0118x; 1.0008x over previous
#include <cuda_runtime.h>
#include <math.h>

#define BATCH 4
#define HW 16384
#define NCH 64
#define C3 192
#define NHEADS 4
#define HD 16
#define NKEY 100

typedef unsigned long long u64;

__device__ __forceinline__ u64 pack2(float a, float b){
  u64 r; asm("mov.b64 %0, {%1, %2};" : "=l"(r) : "f"(a), "f"(b)); return r;
}
__device__ __forceinline__ void fma2(u64 &d, u64 a, u64 b){
  asm("fma.rn.f32x2 %0, %1, %2, %0;" : "+l"(d) : "l"(a), "l"(b));
}
__device__ __forceinline__ void unpack2(u64 a, float &x, float &y){
  asm("mov.b64 {%0, %1}, %2;" : "=f"(x), "=f"(y) : "l"(a));
}
__device__ __forceinline__ float hadd2(u64 a){
  float x, y; unpack2(a, x, y); return x + y;
}
union F4U { float4 f; ulonglong2 u; };

// ---------------- scratch ----------------
__device__ __align__(16) float g_y1[BATCH*C3*HW];
__device__ __align__(16) float g_qkv[BATCH*C3*HW];
__device__ __align__(16) float g_attn[BATCH*NCH*HW];
__device__ __align__(16) float g_out3[BATCH*NCH*HW];
__device__ float g_Sp[BATCH*128*NCH];
__device__ __align__(16) float g_Gpart[BATCH*128*NCH*NCH];
__device__ __align__(16) float g_Gred[16*BATCH*NCH*NCH];
__device__ float g_S[BATCH*NCH];
__device__ int   g_idx[BATCH*NCH];

// ================= tiled GEMM: fused maxpool2 + conv1x1 (64 -> 192) =================
// block = (b, h): 128 pixels. 256 thr: to=tid>>4 (4 outs), tp=tid&15 (px float4s tp & tp+16)
__global__ __launch_bounds__(256) void k_pool_qkv(const float* __restrict__ x,
                                                  const float* __restrict__ wq){
  __shared__ __align__(16) float sA[64*128];   // 32KB, plain row-major [c][px]
  __shared__ __align__(16) float sW[64*64];    // 16KB, Wt[k][o] for current o-tile
  int tid = threadIdx.x;
  int b = blockIdx.x >> 7, h = blockIdx.x & 127;
  float4* sA4 = (float4*)sA;
#pragma unroll
  for (int it = 0; it < 8; it++){
    int idx = tid + it*256;
    int c = idx >> 5, seg = idx & 31;
    const float* base = x + ((b*64+c)<<16) + (h<<9) + (seg<<3);
    float4 f0 = *(const float4*)base;
    float4 f1 = *(const float4*)(base+4);
    float4 g0 = *(const float4*)(base+256);
    float4 g1 = *(const float4*)(base+260);
    float4 q;
    q.x = fmaxf(fmaxf(f0.x,f0.y), fmaxf(g0.x,g0.y));
    q.y = fmaxf(fmaxf(f0.z,f0.w), fmaxf(g0.z,g0.w));
    q.z = fmaxf(fmaxf(f1.x,f1.y), fmaxf(g1.x,g1.y));
    q.w = fmaxf(fmaxf(f1.z,f1.w), fmaxf(g1.z,g1.w));
    sA4[c*32 + seg] = q;
  }
  int to = tid >> 4, tp = tid & 15;
  const float4* sW4 = (const float4*)sW;
  const F4U* sAu = (const F4U*)sA;
  float* outb = g_y1 + b*C3*HW + h*128 + tp*4;
  for (int ot = 0; ot < 3; ot++){
    __syncthreads();
    for (int i = tid; i < 4096; i += 256){
      int o = i >> 6, k = i & 63;
      sW[k*64 + o] = wq[(ot*64 + o)*64 + k];
    }
    __syncthreads();
    u64 acc[4][4];
#pragma unroll
    for (int i = 0; i < 4; i++)
#pragma unroll
      for (int j = 0; j < 4; j++) acc[i][j] = 0ULL;
#pragma unroll 4
    for (int k = 0; k < 64; k++){
      float4 wv = sW4[k*16 + to];
      u64 w0 = pack2(wv.x,wv.x), w1 = pack2(wv.y,wv.y);
      u64 w2 = pack2(wv.z,wv.z), w3 = pack2(wv.w,wv.w);
      F4U a0 = sAu[k*32 + tp];
      F4U a1 = sAu[k*32 + tp + 16];
      fma2(acc[0][0], w0, a0.u.x); fma2(acc[0][1], w0, a0.u.y);
      fma2(acc[0][2], w0, a1.u.x); fma2(acc[0][3], w0, a1.u.y);
      fma2(acc[1][0], w1, a0.u.x); fma2(acc[1][1], w1, a0.u.y);
      fma2(acc[1][2], w1, a1.u.x); fma2(acc[1][3], w1, a1.u.y);
      fma2(acc[2][0], w2, a0.u.x); fma2(acc[2][1], w2, a0.u.y);
      fma2(acc[2][2], w2, a1.u.x); fma2(acc[2][3], w2, a1.u.y);
      fma2(acc[3][0], w3, a0.u.x); fma2(acc[3][1], w3, a0.u.y);
      fma2(acc[3][2], w3, a1.u.x); fma2(acc[3][3], w3, a1.u.y);
    }
#pragma unroll
    for (int i = 0; i < 4; i++){
      int o = ot*64 + to*4 + i;
      ulonglong2 s0; s0.x = acc[i][0]; s0.y = acc[i][1];
      ulonglong2 s1; s1.x = acc[i][2]; s1.y = acc[i][3];
      *(ulonglong2*)(outb + o*HW) = s0;
      *(ulonglong2*)(outb + o*HW + 64) = s1;
    }
  }
}

// ---------------- depthwise 3x3 zero pad, 4 px/thread ----------------
__global__ __launch_bounds__(256) void k_dw3(const float* __restrict__ wd){
  int t = blockIdx.x*256 + threadIdx.x;
  int base = t*4;
  int w4 = base & 127, h = (base>>7)&127, bc = base>>14;
  int ch = bc % C3;
  const float* src = g_y1 + bc*HW;
  const float* kk = wd + ch*9;
  float o0=0.f,o1=0.f,o2=0.f,o3=0.f;
#pragma unroll
  for (int dy = 0; dy < 3; dy++){
    int ih = h + dy - 1;
    if ((unsigned)ih >= 128u) continue;
    const float* r = src + ih*128 + w4;
    float4 m = *(const float4*)r;
    float lf = (w4 > 0)   ? r[-1] : 0.f;
    float rt = (w4 < 124) ? r[4]  : 0.f;
    float ka = kk[dy*3], kb = kk[dy*3+1], kc = kk[dy*3+2];
    o0 = fmaf(lf,ka,fmaf(m.x,kb,fmaf(m.y,kc,o0)));
    o1 = fmaf(m.x,ka,fmaf(m.y,kb,fmaf(m.z,kc,o1)));
    o2 = fmaf(m.y,ka,fmaf(m.z,kb,fmaf(m.w,kc,o2)));
    o3 = fmaf(m.z,ka,fmaf(m.w,kb,fmaf(rt,kc,o3)));
  }
  *(float4*)(g_qkv + base) = make_float4(o0,o1,o2,o3);
}

// ---------------- Gram partials + per-slice channel sums ----------------
__global__ __launch_bounds__(256) void k_gram(){
  __shared__ __align__(16) float sh[64*128];
  int b = blockIdx.y, sp = blockIdx.x;
  int tid = threadIdx.x;
  int tc = (tid >> 4) << 2;
  int td = (tid & 15) << 2;
  const float* qb = g_qkv + b*C3*HW + sp*128;
  float4* sh4 = (float4*)sh;
  for (int i = tid; i < 2048; i += 256){
    int c = i >> 5, nn4 = i & 31;
    sh4[c*32 + (nn4 ^ (c>>2))] = *(const float4*)(qb + c*HW + nn4*4);
  }
  __syncthreads();
  u64 acc[4][4];
#pragma unroll
  for (int i = 0; i < 4; i++)
#pragma unroll
    for (int j = 0; j < 4; j++) acc[i][j] = 0ULL;
  const F4U* shf = (const F4U*)sh;
  for (int nn4 = 0; nn4 < 32; nn4++){
    F4U av[4], bv[4];
#pragma unroll
    for (int i = 0; i < 4; i++){ int r = tc + i; av[i] = shf[r*32 + (nn4 ^ (r>>2))]; }
#pragma unroll
    for (int j = 0; j < 4; j++){ int r = td + j; bv[j] = shf[r*32 + (nn4 ^ (r>>2))]; }
#pragma unroll
    for (int i = 0; i < 4; i++)
#pragma unroll
      for (int j = 0; j < 4; j++){
        fma2(acc[i][j], av[i].u.x, bv[j].u.x);
        fma2(acc[i][j], av[i].u.y, bv[j].u.y);
      }
  }
#pragma unroll
  for (int i = 0; i < 4; i++)
#pragma unroll
    for (int j = 0; j < 4; j++)
      g_Gpart[((b*128+sp)*64 + tc+i)*64 + td+j] = hadd2(acc[i][j]);
  if (tid < 64){
    float s = 0.f;
    for (int nn4 = 0; nn4 < 32; nn4++){
      F4U f = shf[tid*32 + (nn4 ^ (tid>>2))];
      s += (f.f.x + f.f.y) + (f.f.z + f.f.w);
    }
    g_Sp[(b*128+sp)*64 + tid] = s;
  }
}

// ---------------- chip-wide reduction: 16 chunks of 8 slices ----------------
__global__ __launch_bounds__(256) void k_reduce(){
  int t = blockIdx.x*256 + threadIdx.x;      // 262144 threads
  int entry = t & 16383;
  int chunk = t >> 14;                       // 0..15
  int b = entry >> 12, cd = entry & 4095;
  const float* src = g_Gpart + ((size_t)(b*128 + chunk*8))*4096 + cd;
  float s = 0.f;
#pragma unroll
  for (int sp = 0; sp < 8; sp++) s += src[(size_t)sp*4096];
  g_Gred[(size_t)chunk*16384 + entry] = s;
  if (chunk == 0 && cd < 64){
    const float* sq = g_Sp + b*128*64 + cd;
    float ss = 0.f;
#pragma unroll 8
    for (int sp = 0; sp < 128; sp++) ss += sq[sp*64];
    g_S[b*64 + cd] = ss;
  }
}

// ---------------- cov -> sim -> stable ranking ----------------
__global__ void k_stats(){
  __shared__ float covs[64][64];
  __shared__ float stds[64];
  __shared__ float sims[64];
  __shared__ float shS[64];
  int b = blockIdx.x;
  if (threadIdx.x < 64) shS[threadIdx.x] = g_S[b*64 + threadIdx.x];
  __syncthreads();
  for (int pr = threadIdx.x; pr < 4096; pr += 256){
    int c = pr>>6, d = pr&63;
    float g = 0.f;
#pragma unroll
    for (int ch = 0; ch < 16; ch++) g += g_Gred[(size_t)ch*16384 + b*4096 + pr];
    covs[c][d] = g - shS[c]*shS[d]*(1.0f/16384.0f);
  }
  __syncthreads();
  if (threadIdx.x < 64)
    stds[threadIdx.x] = sqrtf(covs[threadIdx.x][threadIdx.x] + 1e-8f);
  __syncthreads();
  if (threadIdx.x < 64){
    int c = threadIdx.x;
    float sc = stds[c], a = 0.f;
    for (int d = 0; d < 64; d++) a += covs[c][d] / fmaxf(sc*stds[d], 1e-8f);
    sims[c] = a * (1.0f/64.0f);
  }
  __syncthreads();
  if (threadIdx.x < 64){
    int c = threadIdx.x;
    float v = sims[c]; int r = 0;
    for (int d = 0; d < 64; d++){
      float u = sims[d];
      r += (u > v) || (u == v && d < c);
    }
    g_idx[b*64 + r] = c;
  }
}

// ---------------- block-local halo attention + gate + scatter (64 thr, round-7) ----------------
__global__ __launch_bounds__(64) void k_attn(const float* __restrict__ gatew,
    const float* __restrict__ gateb, const float* __restrict__ temp,
    const float* __restrict__ relh, const float* __restrict__ relw){
  __shared__ int   sc[HD];
  __shared__ __align__(16) float kn[NKEY][HD];
  __shared__ __align__(16) float vv[NKEY][HD];
  __shared__ __align__(16) float gws[HD*HD];
  __shared__ float gbs[HD];
  int tid = threadIdx.x;
  int g = blockIdx.y, b = blockIdx.z;
  if (tid < HD){
    sc[tid]  = g_idx[b*64 + g*HD + tid];
    gbs[tid] = gateb[g*HD + tid];
  }
  for (int i = tid; i < HD*HD; i += 64) gws[i] = gatew[g*HD*HD + i];
  __syncthreads();
  int bh = blockIdx.x >> 4, bw = blockIdx.x & 15;
  int h0 = bh*8, w0 = bw*8;
  for (int p = tid; p < NKEY; p += 64){
    int ry = p/10, rx = p - ry*10;
    int gh = h0 - 1 + ry, gw2 = w0 - 1 + rx;
    bool inb = ((unsigned)gh < 128u) && ((unsigned)gw2 < 128u);
    int posk = gh*128 + gw2;
    float ss = 0.f; float tmp[HD];
#pragma unroll
    for (int c = 0; c < HD; c++){
      float base = 0.f, vval = 0.f;
      if (inb){
        int off = (b*C3 + sc[c])*HW + posk;
        base = g_qkv[off + 64*HW];
        vval = g_qkv[off + 128*HW];
      }
      float rel = (c < 8) ? relh[(g*10+ry)*8 + c] : relw[(g*10+rx)*8 + (c-8)];
      float kv = base + rel;
      tmp[c] = kv; ss += kv*kv;
      vv[p][c] = vval;
    }
    float inv = 1.0f / fmaxf(sqrtf(ss), 1e-12f);
#pragma unroll
    for (int c = 0; c < HD; c++) kn[p][c] = tmp[c]*inv;
  }
  int qy = tid >> 3, qx = tid & 7;
  int pos = (h0+qy)*128 + (w0+qx);
  float qraw[HD]; float ss = 0.f;
#pragma unroll
  for (int c = 0; c < HD; c++){
    float v = g_qkv[(b*C3 + sc[c])*HW + pos];
    qraw[c] = v; ss += v*v;
  }
  u64 qr2[8];
#pragma unroll
  for (int c = 0; c < HD; c += 2) qr2[c>>1] = pack2(qraw[c], qraw[c+1]);
  float E  = __expf(temp[g]);
  float qs = E / fmaxf(sqrtf(ss), 1e-12f);
  __syncthreads();
  float s = 0.f;
  u64 acc2[8];
#pragma unroll
  for (int i = 0; i < 8; i++) acc2[i] = 0ULL;
#pragma unroll 2
  for (int kp = 0; kp < NKEY; kp++){
    const ulonglong2* kk = (const ulonglong2*)kn[kp];
    ulonglong2 k0 = kk[0], k1 = kk[1], k2 = kk[2], k3 = kk[3];
    u64 da = 0ULL, db = 0ULL;
    fma2(da, qr2[0], k0.x); fma2(db, qr2[1], k0.y);
    fma2(da, qr2[2], k1.x); fma2(db, qr2[3], k1.y);
    fma2(da, qr2[4], k2.x); fma2(db, qr2[5], k2.y);
    fma2(da, qr2[6], k3.x); fma2(db, qr2[7], k3.y);
    float l = (hadd2(da) + hadd2(db)) * qs;
    float pv = __expf(l - E);
    s += pv;
    u64 pv2 = pack2(pv, pv);
    const ulonglong2* vk = (const ulonglong2*)vv[kp];
    ulonglong2 v0 = vk[0], v1 = vk[1], v2 = vk[2], v3 = vk[3];
    fma2(acc2[0], pv2, v0.x); fma2(acc2[1], pv2, v0.y);
    fma2(acc2[2], pv2, v1.x); fma2(acc2[3], pv2, v1.y);
    fma2(acc2[4], pv2, v2.x); fma2(acc2[5], pv2, v2.y);
    fma2(acc2[6], pv2, v3.x); fma2(acc2[7], pv2, v3.y);
  }
  float invs = 1.0f / s;
  float accv[HD];
#pragma unroll
  for (int i = 0; i < 8; i++) unpack2(acc2[i], accv[2*i], accv[2*i+1]);
  const ulonglong2* gw2 = (const ulonglong2*)gws;
#pragma unroll
  for (int o = 0; o < HD; o++){
    u64 a = 0ULL;
#pragma unroll
    for (int cc4 = 0; cc4 < 4; cc4++){
      ulonglong2 w = gw2[o*4 + cc4];
      fma2(a, w.x, qr2[2*cc4]); fma2(a, w.y, qr2[2*cc4+1]);
    }
    float ga = gbs[o] + hadd2(a);
    float sig = 1.0f/(1.0f + __expf(-ga));
    g_attn[(b*NCH + sc[o])*HW + pos] = accv[o]*invs*sig;
  }
}

// ================= fully fused tiled MLP: gate->gelu->down->up(+res)->proj =================
// round-7 mapping: to=tid>>4 (4 outs), tp=tid&15 (px float4s tp & tp+16)
__global__ __launch_bounds__(256) void k_mlp(const float* __restrict__ gw,
    const float* __restrict__ gb, const float* __restrict__ dw,
    const float* __restrict__ db, const float* __restrict__ uw,
    const float* __restrict__ ub, const float* __restrict__ pw){
  __shared__ __align__(16) float sA[64*128];
  __shared__ __align__(16) float sW[64*64];
  int tid = threadIdx.x;
  int b = blockIdx.x >> 7, h = blockIdx.x & 127;
  int pos0 = h*128;
  float4* sA4 = (float4*)sA;
  const F4U* sAu = (const F4U*)sA;
  const float4* sW4 = (const float4*)sW;
  int to = tid >> 4, tp = tid & 15;
  // ---- load mixed = attn_out + q + k ----
#pragma unroll
  for (int it = 0; it < 8; it++){
    int idx = tid + it*256;
    int c = idx >> 5, seg = idx & 31;
    float4 a = ((const float4*)(g_attn + (b*64 + c)*HW + pos0))[seg];
    float4 q = ((const float4*)(g_qkv + (b*192 + c)*HW + pos0))[seg];
    float4 k = ((const float4*)(g_qkv + (b*192 + 64 + c)*HW + pos0))[seg];
    float4 m; m.x=a.x+q.x+k.x; m.y=a.y+q.y+k.y; m.z=a.z+q.z+k.z; m.w=a.w+q.w+k.w;
    sA4[c*32 + seg] = m;
  }
  for (int i = tid; i < 4096; i += 256){
    int o = i >> 6, k = i & 63;
    sW[k*64 + o] = gw[o*64 + k];
  }
  __syncthreads();
  // ---- stage 1: gate (64x64) + gelu*mixed ----
  {
    u64 acc[4][4];
#pragma unroll
    for (int i = 0; i < 4; i++){
      float bv = __ldg(gb + to*4 + i);
      u64 bp = pack2(bv, bv);
#pragma unroll
      for (int j = 0; j < 4; j++) acc[i][j] = bp;
    }
#pragma unroll 4
    for (int k = 0; k < 64; k++){
      float4 wv = sW4[k*16 + to];
      u64 w0 = pack2(wv.x,wv.x), w1 = pack2(wv.y,wv.y);
      u64 w2 = pack2(wv.z,wv.z), w3 = pack2(wv.w,wv.w);
      F4U a0 = sAu[k*32 + tp];
      F4U a1 = sAu[k*32 + tp + 16];
      fma2(acc[0][0], w0, a0.u.x); fma2(acc[0][1], w0, a0.u.y);
      fma2(acc[0][2], w0, a1.u.x); fma2(acc[0][3], w0, a1.u.y);
      fma2(acc[1][0], w1, a0.u.x); fma2(acc[1][1], w1, a0.u.y);
      fma2(acc[1][2], w1, a1.u.x); fma2(acc[1][3], w1, a1.u.y);
      fma2(acc[2][0], w2, a0.u.x); fma2(acc[2][1], w2, a0.u.y);
      fma2(acc[2][2], w2, a1.u.x); fma2(acc[2][3], w2, a1.u.y);
      fma2(acc[3][0], w3, a0.u.x); fma2(acc[3][1], w3, a0.u.y);
      fma2(acc[3][2], w3, a1.u.x); fma2(acc[3][3], w3, a1.u.y);
    }
    __syncthreads();
#pragma unroll
    for (int i = 0; i < 4; i++){
      int o = to*4 + i;
      F4U m0 = sAu[o*32 + tp];
      F4U m1 = sAu[o*32 + tp + 16];
      float v[8];
      unpack2(acc[i][0], v[0], v[1]); unpack2(acc[i][1], v[2], v[3]);
      unpack2(acc[i][2], v[4], v[5]); unpack2(acc[i][3], v[6], v[7]);
      float mm[8];
      mm[0]=m0.f.x; mm[1]=m0.f.y; mm[2]=m0.f.z; mm[3]=m0.f.w;
      mm[4]=m1.f.x; mm[5]=m1.f.y; mm[6]=m1.f.z; mm[7]=m1.f.w;
#pragma unroll
      for (int j = 0; j < 8; j++)
        v[j] = 0.5f*v[j]*(1.0f + erff(v[j]*0.70710678118f)) * mm[j];
      sA4[o*32 + tp]      = make_float4(v[0],v[1],v[2],v[3]);
      sA4[o*32 + tp + 16] = make_float4(v[4],v[5],v[6],v[7]);
    }
  }
  for (int i = tid; i < 2048; i += 256){
    int o = i >> 6, k = i & 63;
    sW[k*32 + o] = dw[o*64 + k];
  }
  __syncthreads();
  // ---- stage 2: down (32x64) ----
  {
    u64 acc[2][4];
#pragma unroll
    for (int i = 0; i < 2; i++){
      float bv = __ldg(db + to*2 + i);
      u64 bp = pack2(bv, bv);
#pragma unroll
      for (int j = 0; j < 4; j++) acc[i][j] = bp;
    }
    const float2* sW2 = (const float2*)sW;
#pragma unroll 4
    for (int k = 0; k < 64; k++){
      float2 wv = sW2[k*16 + to];
      u64 w0 = pack2(wv.x,wv.x), w1 = pack2(wv.y,wv.y);
      F4U a0 = sAu[k*32 + tp];
      F4U a1 = sAu[k*32 + tp + 16];
      fma2(acc[0][0], w0, a0.u.x); fma2(acc[0][1], w0, a0.u.y);
      fma2(acc[0][2], w0, a1.u.x); fma2(acc[0][3], w0, a1.u.y);
      fma2(acc[1][0], w1, a0.u.x); fma2(acc[1][1], w1, a0.u.y);
      fma2(acc[1][2], w1, a1.u.x); fma2(acc[1][3], w1, a1.u.y);
    }
    __syncthreads();
#pragma unroll
    for (int i = 0; i < 2; i++){
      int o = to*2 + i;
      F4U s0, s1;
      s0.u.x = acc[i][0]; s0.u.y = acc[i][1];
      s1.u.x = acc[i][2]; s1.u.y = acc[i][3];
      sA4[o*32 + tp]      = s0.f;
      sA4[o*32 + tp + 16] = s1.f;
    }
  }
  for (int i = tid; i < 2048; i += 256){
    int oo = i & 63; int kk2 = i >> 6;   // kk2 < 32
    sW[kk2*64 + oo] = uw[oo*32 + kk2];
  }
  __syncthreads();
  // ---- stage 3: up (64x32) + attn residual ----
  {
    u64 acc[4][4];
#pragma unroll
    for (int i = 0; i < 4; i++){
      float bv = __ldg(ub + to*4 + i);
      u64 bp = pack2(bv, bv);
#pragma unroll
      for (int j = 0; j < 4; j++) acc[i][j] = bp;
    }
#pragma unroll 4
    for (int k = 0; k < 32; k++){
      float4 wv = sW4[k*16 + to];
      u64 w0 = pack2(wv.x,wv.x), w1 = pack2(wv.y,wv.y);
      u64 w2 = pack2(wv.z,wv.z), w3 = pack2(wv.w,wv.w);
      F4U a0 = sAu[k*32 + tp];
      F4U a1 = sAu[k*32 + tp + 16];
      fma2(acc[0][0], w0, a0.u.x); fma2(acc[0][1], w0, a0.u.y);
      fma2(acc[0][2], w0, a1.u.x); fma2(acc[0][3], w0, a1.u.y);
      fma2(acc[1][0], w1, a0.u.x); fma2(acc[1][1], w1, a0.u.y);
      fma2(acc[1][2], w1, a1.u.x); fma2(acc[1][3], w1, a1.u.y);
      fma2(acc[2][0], w2, a0.u.x); fma2(acc[2][1], w2, a0.u.y);
      fma2(acc[2][2], w2, a1.u.x); fma2(acc[2][3], w2, a1.u.y);
      fma2(acc[3][0], w3, a0.u.x); fma2(acc[3][1], w3, a0.u.y);
      fma2(acc[3][2], w3, a1.u.x); fma2(acc[3][3], w3, a1.u.y);
    }
    __syncthreads();
#pragma unroll
    for (int i = 0; i < 4; i++){
      int o = to*4 + i;
      const float4* ao4 = (const float4*)(g_attn + (b*64 + o)*HW + pos0);
      float4 r0 = ao4[tp], r1 = ao4[tp + 16];
      float v[8];
      unpack2(acc[i][0], v[0], v[1]); unpack2(acc[i][1], v[2], v[3]);
      unpack2(acc[i][2], v[4], v[5]); unpack2(acc[i][3], v[6], v[7]);
      sA4[o*32 + tp]      = make_float4(v[0]+r0.x, v[1]+r0.y, v[2]+r0.z, v[3]+r0.w);
      sA4[o*32 + tp + 16] = make_float4(v[4]+r1.x, v[5]+r1.y, v[6]+r1.z, v[7]+r1.w);
    }
  }
  for (int i = tid; i < 4096; i += 256){
    int o = i >> 6, k = i & 63;
    sW[k*64 + o] = pw[o*64 + k];
  }
  __syncthreads();
  // ---- stage 4: proj (64x64) ----
  {
    u64 acc[4][4];
#pragma unroll
    for (int i = 0; i < 4; i++)
#pragma unroll
      for (int j = 0; j < 4; j++) acc[i][j] = 0ULL;
#pragma unroll 4
    for (int k = 0; k < 64; k++){
      float4 wv = sW4[k*16 + to];
      u64 w0 = pack2(wv.x,wv.x), w1 = pack2(wv.y,wv.y);
      u64 w2 = pack2(wv.z,wv.z), w3 = pack2(wv.w,wv.w);
      F4U a0 = sAu[k*32 + tp];
      F4U a1 = sAu[k*32 + tp + 16];
      fma2(acc[0][0], w0, a0.u.x); fma2(acc[0][1], w0, a0.u.y);
      fma2(acc[0][2], w0, a1.u.x); fma2(acc[0][3], w0, a1.u.y);
      fma2(acc[1][0], w1, a0.u.x); fma2(acc[1][1], w1, a0.u.y);
      fma2(acc[1][2], w1, a1.u.x); fma2(acc[1][3], w1, a1.u.y);
      fma2(acc[2][0], w2, a0.u.x); fma2(acc[2][1], w2, a0.u.y);
      fma2(acc[2][2], w2, a1.u.x); fma2(acc[2][3], w2, a1.u.y);
      fma2(acc[3][0], w3, a0.u.x); fma2(acc[3][1], w3, a0.u.y);
      fma2(acc[3][2], w3, a1.u.x); fma2(acc[3][3], w3, a1.u.y);
    }
    float* outb = g_out3 + b*NCH*HW + pos0 + tp*4;
#pragma unroll
    for (int i = 0; i < 4; i++){
      int o = to*4 + i;
      ulonglong2 s0; s0.x = acc[i][0]; s0.y = acc[i][1];
      ulonglong2 s1; s1.x = acc[i][2]; s1.y = acc[i][3];
      *(ulonglong2*)(outb + o*HW) = s0;
      *(ulonglong2*)(outb + o*HW + 64) = s1;
    }
  }
}

// ============ fused: depthwise 3x3 reflect + bias + bilinear x2 upsample ============
__global__ __launch_bounds__(256) void k_lpup(const float* __restrict__ wl,
                                              const float* __restrict__ bl,
                                              float* __restrict__ outp){
  __shared__ __align__(16) float sout[12*128];
  __shared__ float slp[10*128];
  int bc = blockIdx.x >> 4;
  int yt = blockIdx.x & 15;
  int ch = bc & 63;
  int Y0 = yt*16;
  int rmin = (Y0*127)/255;
  const float* src = g_out3 + bc*HW;
  int tid = threadIdx.x;
  float4* sout4 = (float4*)sout;
  for (int i = tid; i < 384; i += 256){
    int j = i >> 5, seg = i & 31;
    int r = rmin - 1 + j;
    r = (r < 0) ? -r : ((r > 127) ? 254 - r : r);
    sout4[j*32 + seg] = ((const float4*)(src + r*128))[seg];
  }
  float bv = bl[ch];
  float k0=wl[ch*9],k1=wl[ch*9+1],k2=wl[ch*9+2],k3=wl[ch*9+3],k4=wl[ch*9+4],
        k5=wl[ch*9+5],k6=wl[ch*9+6],k7=wl[ch*9+7],k8=wl[ch*9+8];
  __syncthreads();
  for (int i = tid; i < 1280; i += 256){
    int j = i >> 7, w = i & 127;
    int wl_ = (w > 0)   ? w-1 : 1;
    int wr_ = (w < 127) ? w+1 : 126;
    const float* r0 = sout + j*128;
    const float* r1 = r0 + 128;
    const float* r2 = r1 + 128;
    float acc = bv;
    acc = fmaf(r0[wl_],k0,fmaf(r0[w],k1,fmaf(r0[wr_],k2,acc)));
    acc = fmaf(r1[wl_],k3,fmaf(r1[w],k4,fmaf(r1[wr_],k5,acc)));
    acc = fmaf(r2[wl_],k6,fmaf(r2[w],k7,fmaf(r2[wr_],k8,acc)));
    slp[j*128 + w] = acc;
  }
  __syncthreads();
  int row = tid >> 4;
  int Y = Y0 + row;
  float cy = Y * (127.0f/255.0f);
  int y0 = (int)cy; if (y0 > 126) y0 = 126;
  float wy = cy - (float)y0;
  int ly = y0 - rmin;
  const float* t0 = slp + ly*128;
  const float* t1 = t0 + 128;
  float* orow = outp + (size_t)bc*65536 + Y*256 + (tid&15)*16;
#pragma unroll
  for (int v = 0; v < 4; v++){
    float4 res;
#pragma unroll
    for (int i2 = 0; i2 < 4; i2++){
      int X = (tid&15)*16 + v*4 + i2;
      float cx = X * (127.0f/255.0f);
      int x0 = (int)cx; if (x0 > 126) x0 = 126;
      float wx = cx - (float)x0;
      float v00 = t0[x0], v01 = t0[x0+1];
      float v10 = t1[x0], v11 = t1[x0+1];
      float u0 = v00 + (v10 - v00)*wy;
      float u1 = v01 + (v11 - v01)*wy;
      ((float*)&res)[i2] = u0 + (u1 - u0)*wx;
    }
    *(float4*)(orow + v*4) = res;
  }
}

// ---------------- launch ----------------
extern "C" void kernel_launch(void* const* d_in, const int* in_sizes, int n_in,
                              void* d_out, int out_size){
  const float* x     = (const float*)d_in[0];
  const float* qkvw  = (const float*)d_in[1];
  const float* lcew  = (const float*)d_in[2];
  const float* gatew = (const float*)d_in[3];
  const float* gateb = (const float*)d_in[4];
  const float* temp  = (const float*)d_in[5];
  const float* relh  = (const float*)d_in[6];
  const float* relw  = (const float*)d_in[7];
  const float* downw = (const float*)d_in[8];
  const float* downb = (const float*)d_in[9];
  const float* upw   = (const float*)d_in[10];
  const float* upb   = (const float*)d_in[11];
  const float* gatingw = (const float*)d_in[12];
  const float* gatingb = (const float*)d_in[13];
  const float* projw = (const float*)d_in[14];
  const float* lpw   = (const float*)d_in[15];
  const float* lpb   = (const float*)d_in[16];
  float* outp = (float*)d_out;

  k_pool_qkv<<<512, 256>>>(x, qkvw);
  k_dw3<<<(BATCH*C3*HW)/1024, 256>>>(lcew);
  k_gram<<<dim3(128, BATCH), 256>>>();
  k_reduce<<<1024, 256>>>();
  k_stats<<<BATCH, 256>>>();
  k_attn<<<dim3(256, NHEADS, BATCH), 64>>>(gatew, gateb, temp, relh, relw);
  k_mlp<<<512, 256>>>(gatingw, gatingb, downw, downb, upw, upb, projw);
  k_lpup<<<BATCH*NCH*16, 256>>>(lpw, lpb, outp);
}

// round 13
// speedup vs baseline: 1.1577x; 1.1441x over previous
#include <cuda_runtime.h>
#include <math.h>

#define BATCH 4
#define HW 16384
#define NCH 64
#define C3 192
#define NHEADS 4
#define HD 16
#define NKEY 100

typedef unsigned long long u64;

__device__ __forceinline__ u64 pack2(float a, float b){
  u64 r; asm("mov.b64 %0, {%1, %2};" : "=l"(r) : "f"(a), "f"(b)); return r;
}
__device__ __forceinline__ void fma2(u64 &d, u64 a, u64 b){
  asm("fma.rn.f32x2 %0, %1, %2, %0;" : "+l"(d) : "l"(a), "l"(b));
}
__device__ __forceinline__ void unpack2(u64 a, float &x, float &y){
  asm("mov.b64 {%0, %1}, %2;" : "=f"(x), "=f"(y) : "l"(a));
}
__device__ __forceinline__ float hadd2(u64 a){
  float x, y; unpack2(a, x, y); return x + y;
}
union F4U { float4 f; ulonglong2 u; };

// ---------------- scratch ----------------
__device__ __align__(16) float g_y1[BATCH*C3*HW];
__device__ __align__(16) float g_qkv[BATCH*C3*HW];
__device__ __align__(16) float g_attn[BATCH*NCH*HW];
__device__ __align__(16) float g_out3[BATCH*NCH*HW];
__device__ __align__(16) float g_lp[BATCH*NCH*HW];
__device__ float g_Sp[BATCH*128*NCH];
__device__ __align__(16) float g_Gpart[BATCH*128*NCH*NCH];
__device__ __align__(16) float g_Gred[16*BATCH*NCH*NCH];
__device__ float g_Sred[16*BATCH*NCH];
__device__ int   g_idx[BATCH*NCH];

// ================= tiled GEMM: fused maxpool2 + conv1x1 (64 -> 192) =================
__global__ __launch_bounds__(256) void k_pool_qkv(const float* __restrict__ x,
                                                  const float* __restrict__ wq){
  __shared__ __align__(16) float sA[64*128];
  __shared__ __align__(16) float sW[64*64];
  int tid = threadIdx.x;
  int b = blockIdx.x >> 7, h = blockIdx.x & 127;
  float4* sA4 = (float4*)sA;
#pragma unroll
  for (int it = 0; it < 8; it++){
    int idx = tid + it*256;
    int c = idx >> 5, seg = idx & 31;
    const float* base = x + ((b*64+c)<<16) + (h<<9) + (seg<<3);
    float4 f0 = *(const float4*)base;
    float4 f1 = *(const float4*)(base+4);
    float4 g0 = *(const float4*)(base+256);
    float4 g1 = *(const float4*)(base+260);
    float4 q;
    q.x = fmaxf(fmaxf(f0.x,f0.y), fmaxf(g0.x,g0.y));
    q.y = fmaxf(fmaxf(f0.z,f0.w), fmaxf(g0.z,g0.w));
    q.z = fmaxf(fmaxf(f1.x,f1.y), fmaxf(g1.x,g1.y));
    q.w = fmaxf(fmaxf(f1.z,f1.w), fmaxf(g1.z,g1.w));
    sA4[c*32 + seg] = q;
  }
  int to = tid >> 4, tp = tid & 15;
  const float4* sW4 = (const float4*)sW;
  const F4U* sAu = (const F4U*)sA;
  float* outb = g_y1 + b*C3*HW + h*128 + tp*4;
  for (int ot = 0; ot < 3; ot++){
    __syncthreads();
    for (int i = tid; i < 4096; i += 256){
      int o = i >> 6, k = i & 63;
      sW[k*64 + o] = wq[(ot*64 + o)*64 + k];
    }
    __syncthreads();
    u64 acc[4][4];
#pragma unroll
    for (int i = 0; i < 4; i++)
#pragma unroll
      for (int j = 0; j < 4; j++) acc[i][j] = 0ULL;
#pragma unroll 4
    for (int k = 0; k < 64; k++){
      float4 wv = sW4[k*16 + to];
      u64 w0 = pack2(wv.x,wv.x), w1 = pack2(wv.y,wv.y);
      u64 w2 = pack2(wv.z,wv.z), w3 = pack2(wv.w,wv.w);
      F4U a0 = sAu[k*32 + tp];
      F4U a1 = sAu[k*32 + tp + 16];
      fma2(acc[0][0], w0, a0.u.x); fma2(acc[0][1], w0, a0.u.y);
      fma2(acc[0][2], w0, a1.u.x); fma2(acc[0][3], w0, a1.u.y);
      fma2(acc[1][0], w1, a0.u.x); fma2(acc[1][1], w1, a0.u.y);
      fma2(acc[1][2], w1, a1.u.x); fma2(acc[1][3], w1, a1.u.y);
      fma2(acc[2][0], w2, a0.u.x); fma2(acc[2][1], w2, a0.u.y);
      fma2(acc[2][2], w2, a1.u.x); fma2(acc[2][3], w2, a1.u.y);
      fma2(acc[3][0], w3, a0.u.x); fma2(acc[3][1], w3, a0.u.y);
      fma2(acc[3][2], w3, a1.u.x); fma2(acc[3][3], w3, a1.u.y);
    }
#pragma unroll
    for (int i = 0; i < 4; i++){
      int o = ot*64 + to*4 + i;
      ulonglong2 s0; s0.x = acc[i][0]; s0.y = acc[i][1];
      ulonglong2 s1; s1.x = acc[i][2]; s1.y = acc[i][3];
      *(ulonglong2*)(outb + o*HW) = s0;
      *(ulonglong2*)(outb + o*HW + 64) = s1;
    }
  }
}

// ---------------- depthwise 3x3 zero pad, 4 px/thread ----------------
__global__ __launch_bounds__(256) void k_dw3(const float* __restrict__ wd){
  int t = blockIdx.x*256 + threadIdx.x;
  int base = t*4;
  int w4 = base & 127, h = (base>>7)&127, bc = base>>14;
  int ch = bc % C3;
  const float* src = g_y1 + bc*HW;
  const float* kk = wd + ch*9;
  float o0=0.f,o1=0.f,o2=0.f,o3=0.f;
#pragma unroll
  for (int dy = 0; dy < 3; dy++){
    int ih = h + dy - 1;
    if ((unsigned)ih >= 128u) continue;
    const float* r = src + ih*128 + w4;
    float4 m = *(const float4*)r;
    float lf = (w4 > 0)   ? r[-1] : 0.f;
    float rt = (w4 < 124) ? r[4]  : 0.f;
    float ka = kk[dy*3], kb = kk[dy*3+1], kc = kk[dy*3+2];
    o0 = fmaf(lf,ka,fmaf(m.x,kb,fmaf(m.y,kc,o0)));
    o1 = fmaf(m.x,ka,fmaf(m.y,kb,fmaf(m.z,kc,o1)));
    o2 = fmaf(m.y,ka,fmaf(m.z,kb,fmaf(m.w,kc,o2)));
    o3 = fmaf(m.z,ka,fmaf(m.w,kb,fmaf(rt,kc,o3)));
  }
  *(float4*)(g_qkv + base) = make_float4(o0,o1,o2,o3);
}

// ---------------- Gram partials + per-slice channel sums ----------------
__global__ __launch_bounds__(256) void k_gram(){
  __shared__ __align__(16) float sh[64*128];
  int b = blockIdx.y, sp = blockIdx.x;
  int tid = threadIdx.x;
  int tc = (tid >> 4) << 2;
  int td = (tid & 15) << 2;
  const float* qb = g_qkv + b*C3*HW + sp*128;
  float4* sh4 = (float4*)sh;
  for (int i = tid; i < 2048; i += 256){
    int c = i >> 5, nn4 = i & 31;
    sh4[c*32 + (nn4 ^ (c>>2))] = *(const float4*)(qb + c*HW + nn4*4);
  }
  __syncthreads();
  u64 acc[4][4];
#pragma unroll
  for (int i = 0; i < 4; i++)
#pragma unroll
    for (int j = 0; j < 4; j++) acc[i][j] = 0ULL;
  const F4U* shf = (const F4U*)sh;
  for (int nn4 = 0; nn4 < 32; nn4++){
    F4U av[4], bv[4];
#pragma unroll
    for (int i = 0; i < 4; i++){ int r = tc + i; av[i] = shf[r*32 + (nn4 ^ (r>>2))]; }
#pragma unroll
    for (int j = 0; j < 4; j++){ int r = td + j; bv[j] = shf[r*32 + (nn4 ^ (r>>2))]; }
#pragma unroll
    for (int i = 0; i < 4; i++)
#pragma unroll
      for (int j = 0; j < 4; j++){
        fma2(acc[i][j], av[i].u.x, bv[j].u.x);
        fma2(acc[i][j], av[i].u.y, bv[j].u.y);
      }
  }
#pragma unroll
  for (int i = 0; i < 4; i++)
#pragma unroll
    for (int j = 0; j < 4; j++)
      g_Gpart[((b*128+sp)*64 + tc+i)*64 + td+j] = hadd2(acc[i][j]);
  if (tid < 64){
    float s = 0.f;
    for (int nn4 = 0; nn4 < 32; nn4++){
      F4U f = shf[tid*32 + (nn4 ^ (tid>>2))];
      s += (f.f.x + f.f.y) + (f.f.z + f.f.w);
    }
    g_Sp[(b*128+sp)*64 + tid] = s;
  }
}

// ---------------- chip-wide reduction: 16 chunks of 8 slices; parallel S partials ----------------
__global__ __launch_bounds__(256) void k_reduce(){
  int t = blockIdx.x*256 + threadIdx.x;      // 262144 threads
  int entry = t & 16383;
  int chunk = t >> 14;                       // 0..15
  int b = entry >> 12, cd = entry & 4095;
  const float* src = g_Gpart + ((size_t)(b*128 + chunk*8))*4096 + cd;
  float s = 0.f;
#pragma unroll
  for (int sp = 0; sp < 8; sp++) s += src[(size_t)sp*4096];
  g_Gred[(size_t)chunk*16384 + entry] = s;
  if (cd < 64){
    const float* sq = g_Sp + (b*128 + chunk*8)*64 + cd;
    float ss = 0.f;
#pragma unroll
    for (int sp = 0; sp < 8; sp++) ss += sq[sp*64];
    g_Sred[(chunk*BATCH + b)*64 + cd] = ss;
  }
}

// ---------------- cov -> sim -> stable ranking ----------------
__global__ void k_stats(){
  __shared__ float covs[64][64];
  __shared__ float stds[64];
  __shared__ float sims[64];
  __shared__ float shS[64];
  int b = blockIdx.x;
  if (threadIdx.x < 64){
    float s = 0.f;
#pragma unroll
    for (int ch = 0; ch < 16; ch++) s += g_Sred[(ch*BATCH + b)*64 + threadIdx.x];
    shS[threadIdx.x] = s;
  }
  __syncthreads();
  for (int pr = threadIdx.x; pr < 4096; pr += 256){
    int c = pr>>6, d = pr&63;
    float g = 0.f;
#pragma unroll
    for (int ch = 0; ch < 16; ch++) g += g_Gred[(size_t)ch*16384 + b*4096 + pr];
    covs[c][d] = g - shS[c]*shS[d]*(1.0f/16384.0f);
  }
  __syncthreads();
  if (threadIdx.x < 64)
    stds[threadIdx.x] = sqrtf(covs[threadIdx.x][threadIdx.x] + 1e-8f);
  __syncthreads();
  if (threadIdx.x < 64){
    int c = threadIdx.x;
    float sc = stds[c], a = 0.f;
    for (int d = 0; d < 64; d++) a += covs[c][d] / fmaxf(sc*stds[d], 1e-8f);
    sims[c] = a * (1.0f/64.0f);
  }
  __syncthreads();
  if (threadIdx.x < 64){
    int c = threadIdx.x;
    float v = sims[c]; int r = 0;
    for (int d = 0; d < 64; d++){
      float u = sims[d];
      r += (u > v) || (u == v && d < c);
    }
    g_idx[b*64 + r] = c;
  }
}

// ---------------- block-local halo attention + gate + scatter (64 thr) ----------------
__global__ __launch_bounds__(64) void k_attn(const float* __restrict__ gatew,
    const float* __restrict__ gateb, const float* __restrict__ temp,
    const float* __restrict__ relh, const float* __restrict__ relw){
  __shared__ int   sc[HD];
  __shared__ __align__(16) float kn[NKEY][HD];
  __shared__ __align__(16) float vv[NKEY][HD];
  __shared__ __align__(16) float gws[HD*HD];
  __shared__ float gbs[HD];
  int tid = threadIdx.x;
  int g = blockIdx.y, b = blockIdx.z;
  if (tid < HD){
    sc[tid]  = g_idx[b*64 + g*HD + tid];
    gbs[tid] = gateb[g*HD + tid];
  }
  for (int i = tid; i < HD*HD; i += 64) gws[i] = gatew[g*HD*HD + i];
  __syncthreads();
  int bh = blockIdx.x >> 4, bw = blockIdx.x & 15;
  int h0 = bh*8, w0 = bw*8;
  for (int p = tid; p < NKEY; p += 64){
    int ry = p/10, rx = p - ry*10;
    int gh = h0 - 1 + ry, gw2 = w0 - 1 + rx;
    bool inb = ((unsigned)gh < 128u) && ((unsigned)gw2 < 128u);
    int posk = gh*128 + gw2;
    float ss = 0.f; float tmp[HD];
#pragma unroll
    for (int c = 0; c < HD; c++){
      float base = 0.f, vval = 0.f;
      if (inb){
        int off = (b*C3 + sc[c])*HW + posk;
        base = g_qkv[off + 64*HW];
        vval = g_qkv[off + 128*HW];
      }
      float rel = (c < 8) ? relh[(g*10+ry)*8 + c] : relw[(g*10+rx)*8 + (c-8)];
      float kv = base + rel;
      tmp[c] = kv; ss += kv*kv;
      vv[p][c] = vval;
    }
    float inv = 1.0f / fmaxf(sqrtf(ss), 1e-12f);
#pragma unroll
    for (int c = 0; c < HD; c++) kn[p][c] = tmp[c]*inv;
  }
  int qy = tid >> 3, qx = tid & 7;
  int pos = (h0+qy)*128 + (w0+qx);
  float qraw[HD]; float ss = 0.f;
#pragma unroll
  for (int c = 0; c < HD; c++){
    float v = g_qkv[(b*C3 + sc[c])*HW + pos];
    qraw[c] = v; ss += v*v;
  }
  u64 qr2[8];
#pragma unroll
  for (int c = 0; c < HD; c += 2) qr2[c>>1] = pack2(qraw[c], qraw[c+1]);
  float E  = __expf(temp[g]);
  float qs = E / fmaxf(sqrtf(ss), 1e-12f);
  __syncthreads();
  float s = 0.f;
  u64 acc2[8];
#pragma unroll
  for (int i = 0; i < 8; i++) acc2[i] = 0ULL;
#pragma unroll 2
  for (int kp = 0; kp < NKEY; kp++){
    const ulonglong2* kk = (const ulonglong2*)kn[kp];
    ulonglong2 k0 = kk[0], k1 = kk[1], k2 = kk[2], k3 = kk[3];
    u64 da = 0ULL, db = 0ULL;
    fma2(da, qr2[0], k0.x); fma2(db, qr2[1], k0.y);
    fma2(da, qr2[2], k1.x); fma2(db, qr2[3], k1.y);
    fma2(da, qr2[4], k2.x); fma2(db, qr2[5], k2.y);
    fma2(da, qr2[6], k3.x); fma2(db, qr2[7], k3.y);
    float l = (hadd2(da) + hadd2(db)) * qs;
    float pv = __expf(l - E);
    s += pv;
    u64 pv2 = pack2(pv, pv);
    const ulonglong2* vk = (const ulonglong2*)vv[kp];
    ulonglong2 v0 = vk[0], v1 = vk[1], v2 = vk[2], v3 = vk[3];
    fma2(acc2[0], pv2, v0.x); fma2(acc2[1], pv2, v0.y);
    fma2(acc2[2], pv2, v1.x); fma2(acc2[3], pv2, v1.y);
    fma2(acc2[4], pv2, v2.x); fma2(acc2[5], pv2, v2.y);
    fma2(acc2[6], pv2, v3.x); fma2(acc2[7], pv2, v3.y);
  }
  float invs = 1.0f / s;
  float accv[HD];
#pragma unroll
  for (int i = 0; i < 8; i++) unpack2(acc2[i], accv[2*i], accv[2*i+1]);
  const ulonglong2* gw2 = (const ulonglong2*)gws;
#pragma unroll
  for (int o = 0; o < HD; o++){
    u64 a = 0ULL;
#pragma unroll
    for (int cc4 = 0; cc4 < 4; cc4++){
      ulonglong2 w = gw2[o*4 + cc4];
      fma2(a, w.x, qr2[2*cc4]); fma2(a, w.y, qr2[2*cc4+1]);
    }
    float ga = gbs[o] + hadd2(a);
    float sig = 1.0f/(1.0f + __expf(-ga));
    g_attn[(b*NCH + sc[o])*HW + pos] = accv[o]*invs*sig;
  }
}

// ================= fully fused tiled MLP: gate->gelu->down->up(+res)->proj =================
__global__ __launch_bounds__(256) void k_mlp(const float* __restrict__ gw,
    const float* __restrict__ gb, const float* __restrict__ dw,
    const float* __restrict__ db, const float* __restrict__ uw,
    const float* __restrict__ ub, const float* __restrict__ pw){
  __shared__ __align__(16) float sA[64*128];
  __shared__ __align__(16) float sW[64*64];
  int tid = threadIdx.x;
  int b = blockIdx.x >> 7, h = blockIdx.x & 127;
  int pos0 = h*128;
  float4* sA4 = (float4*)sA;
  const F4U* sAu = (const F4U*)sA;
  const float4* sW4 = (const float4*)sW;
  int to = tid >> 4, tp = tid & 15;
#pragma unroll
  for (int it = 0; it < 8; it++){
    int idx = tid + it*256;
    int c = idx >> 5, seg = idx & 31;
    float4 a = ((const float4*)(g_attn + (b*64 + c)*HW + pos0))[seg];
    float4 q = ((const float4*)(g_qkv + (b*192 + c)*HW + pos0))[seg];
    float4 k = ((const float4*)(g_qkv + (b*192 + 64 + c)*HW + pos0))[seg];
    float4 m; m.x=a.x+q.x+k.x; m.y=a.y+q.y+k.y; m.z=a.z+q.z+k.z; m.w=a.w+q.w+k.w;
    sA4[c*32 + seg] = m;
  }
  for (int i = tid; i < 4096; i += 256){
    int o = i >> 6, k = i & 63;
    sW[k*64 + o] = gw[o*64 + k];
  }
  __syncthreads();
  // ---- stage 1: gate (64x64) + gelu*mixed ----
  {
    u64 acc[4][4];
#pragma unroll
    for (int i = 0; i < 4; i++){
      float bv = __ldg(gb + to*4 + i);
      u64 bp = pack2(bv, bv);
#pragma unroll
      for (int j = 0; j < 4; j++) acc[i][j] = bp;
    }
#pragma unroll 4
    for (int k = 0; k < 64; k++){
      float4 wv = sW4[k*16 + to];
      u64 w0 = pack2(wv.x,wv.x), w1 = pack2(wv.y,wv.y);
      u64 w2 = pack2(wv.z,wv.z), w3 = pack2(wv.w,wv.w);
      F4U a0 = sAu[k*32 + tp];
      F4U a1 = sAu[k*32 + tp + 16];
      fma2(acc[0][0], w0, a0.u.x); fma2(acc[0][1], w0, a0.u.y);
      fma2(acc[0][2], w0, a1.u.x); fma2(acc[0][3], w0, a1.u.y);
      fma2(acc[1][0], w1, a0.u.x); fma2(acc[1][1], w1, a0.u.y);
      fma2(acc[1][2], w1, a1.u.x); fma2(acc[1][3], w1, a1.u.y);
      fma2(acc[2][0], w2, a0.u.x); fma2(acc[2][1], w2, a0.u.y);
      fma2(acc[2][2], w2, a1.u.x); fma2(acc[2][3], w2, a1.u.y);
      fma2(acc[3][0], w3, a0.u.x); fma2(acc[3][1], w3, a0.u.y);
      fma2(acc[3][2], w3, a1.u.x); fma2(acc[3][3], w3, a1.u.y);
    }
    __syncthreads();
#pragma unroll
    for (int i = 0; i < 4; i++){
      int o = to*4 + i;
      F4U m0 = sAu[o*32 + tp];
      F4U m1 = sAu[o*32 + tp + 16];
      float v[8];
      unpack2(acc[i][0], v[0], v[1]); unpack2(acc[i][1], v[2], v[3]);
      unpack2(acc[i][2], v[4], v[5]); unpack2(acc[i][3], v[6], v[7]);
      float mm[8];
      mm[0]=m0.f.x; mm[1]=m0.f.y; mm[2]=m0.f.z; mm[3]=m0.f.w;
      mm[4]=m1.f.x; mm[5]=m1.f.y; mm[6]=m1.f.z; mm[7]=m1.f.w;
#pragma unroll
      for (int j = 0; j < 8; j++)
        v[j] = 0.5f*v[j]*(1.0f + erff(v[j]*0.70710678118f)) * mm[j];
      sA4[o*32 + tp]      = make_float4(v[0],v[1],v[2],v[3]);
      sA4[o*32 + tp + 16] = make_float4(v[4],v[5],v[6],v[7]);
    }
  }
  for (int i = tid; i < 2048; i += 256){
    int o = i >> 6, k = i & 63;
    sW[k*32 + o] = dw[o*64 + k];
  }
  __syncthreads();
  // ---- stage 2: down (32x64) ----
  {
    u64 acc[2][4];
#pragma unroll
    for (int i = 0; i < 2; i++){
      float bv = __ldg(db + to*2 + i);
      u64 bp = pack2(bv, bv);
#pragma unroll
      for (int j = 0; j < 4; j++) acc[i][j] = bp;
    }
    const float2* sW2 = (const float2*)sW;
#pragma unroll 4
    for (int k = 0; k < 64; k++){
      float2 wv = sW2[k*16 + to];
      u64 w0 = pack2(wv.x,wv.x), w1 = pack2(wv.y,wv.y);
      F4U a0 = sAu[k*32 + tp];
      F4U a1 = sAu[k*32 + tp + 16];
      fma2(acc[0][0], w0, a0.u.x); fma2(acc[0][1], w0, a0.u.y);
      fma2(acc[0][2], w0, a1.u.x); fma2(acc[0][3], w0, a1.u.y);
      fma2(acc[1][0], w1, a0.u.x); fma2(acc[1][1], w1, a0.u.y);
      fma2(acc[1][2], w1, a1.u.x); fma2(acc[1][3], w1, a1.u.y);
    }
    __syncthreads();
#pragma unroll
    for (int i = 0; i < 2; i++){
      int o = to*2 + i;
      F4U s0, s1;
      s0.u.x = acc[i][0]; s0.u.y = acc[i][1];
      s1.u.x = acc[i][2]; s1.u.y = acc[i][3];
      sA4[o*32 + tp]      = s0.f;
      sA4[o*32 + tp + 16] = s1.f;
    }
  }
  for (int i = tid; i < 2048; i += 256){
    int oo = i & 63; int kk2 = i >> 6;   // kk2 < 32
    sW[kk2*64 + oo] = uw[oo*32 + kk2];
  }
  __syncthreads();
  // ---- stage 3: up (64x32) + attn residual ----
  {
    u64 acc[4][4];
#pragma unroll
    for (int i = 0; i < 4; i++){
      float bv = __ldg(ub + to*4 + i);
      u64 bp = pack2(bv, bv);
#pragma unroll
      for (int j = 0; j < 4; j++) acc[i][j] = bp;
    }
#pragma unroll 4
    for (int k = 0; k < 32; k++){
      float4 wv = sW4[k*16 + to];
      u64 w0 = pack2(wv.x,wv.x), w1 = pack2(wv.y,wv.y);
      u64 w2 = pack2(wv.z,wv.z), w3 = pack2(wv.w,wv.w);
      F4U a0 = sAu[k*32 + tp];
      F4U a1 = sAu[k*32 + tp + 16];
      fma2(acc[0][0], w0, a0.u.x); fma2(acc[0][1], w0, a0.u.y);
      fma2(acc[0][2], w0, a1.u.x); fma2(acc[0][3], w0, a1.u.y);
      fma2(acc[1][0], w1, a0.u.x); fma2(acc[1][1], w1, a0.u.y);
      fma2(acc[1][2], w1, a1.u.x); fma2(acc[1][3], w1, a1.u.y);
      fma2(acc[2][0], w2, a0.u.x); fma2(acc[2][1], w2, a0.u.y);
      fma2(acc[2][2], w2, a1.u.x); fma2(acc[2][3], w2, a1.u.y);
      fma2(acc[3][0], w3, a0.u.x); fma2(acc[3][1], w3, a0.u.y);
      fma2(acc[3][2], w3, a1.u.x); fma2(acc[3][3], w3, a1.u.y);
    }
    __syncthreads();
#pragma unroll
    for (int i = 0; i < 4; i++){
      int o = to*4 + i;
      const float4* ao4 = (const float4*)(g_attn + (b*64 + o)*HW + pos0);
      float4 r0 = ao4[tp], r1 = ao4[tp + 16];
      float v[8];
      unpack2(acc[i][0], v[0], v[1]); unpack2(acc[i][1], v[2], v[3]);
      unpack2(acc[i][2], v[4], v[5]); unpack2(acc[i][3], v[6], v[7]);
      sA4[o*32 + tp]      = make_float4(v[0]+r0.x, v[1]+r0.y, v[2]+r0.z, v[3]+r0.w);
      sA4[o*32 + tp + 16] = make_float4(v[4]+r1.x, v[5]+r1.y, v[6]+r1.z, v[7]+r1.w);
    }
  }
  for (int i = tid; i < 4096; i += 256){
    int o = i >> 6, k = i & 63;
    sW[k*64 + o] = pw[o*64 + k];
  }
  __syncthreads();
  // ---- stage 4: proj (64x64) ----
  {
    u64 acc[4][4];
#pragma unroll
    for (int i = 0; i < 4; i++)
#pragma unroll
      for (int j = 0; j < 4; j++) acc[i][j] = 0ULL;
#pragma unroll 4
    for (int k = 0; k < 64; k++){
      float4 wv = sW4[k*16 + to];
      u64 w0 = pack2(wv.x,wv.x), w1 = pack2(wv.y,wv.y);
      u64 w2 = pack2(wv.z,wv.z), w3 = pack2(wv.w,wv.w);
      F4U a0 = sAu[k*32 + tp];
      F4U a1 = sAu[k*32 + tp + 16];
      fma2(acc[0][0], w0, a0.u.x); fma2(acc[0][1], w0, a0.u.y);
      fma2(acc[0][2], w0, a1.u.x); fma2(acc[0][3], w0, a1.u.y);
      fma2(acc[1][0], w1, a0.u.x); fma2(acc[1][1], w1, a0.u.y);
      fma2(acc[1][2], w1, a1.u.x); fma2(acc[1][3], w1, a1.u.y);
      fma2(acc[2][0], w2, a0.u.x); fma2(acc[2][1], w2, a0.u.y);
      fma2(acc[2][2], w2, a1.u.x); fma2(acc[2][3], w2, a1.u.y);
      fma2(acc[3][0], w3, a0.u.x); fma2(acc[3][1], w3, a0.u.y);
      fma2(acc[3][2], w3, a1.u.x); fma2(acc[3][3], w3, a1.u.y);
    }
    float* outb = g_out3 + b*NCH*HW + pos0 + tp*4;
#pragma unroll
    for (int i = 0; i < 4; i++){
      int o = to*4 + i;
      ulonglong2 s0; s0.x = acc[i][0]; s0.y = acc[i][1];
      ulonglong2 s1; s1.x = acc[i][2]; s1.y = acc[i][3];
      *(ulonglong2*)(outb + o*HW) = s0;
      *(ulonglong2*)(outb + o*HW + 64) = s1;
    }
  }
}

// ---------------- depthwise 3x3 reflect + bias, 4 px/thread ----------------
__global__ __launch_bounds__(256) void k_lp(const float* __restrict__ wl,
                                            const float* __restrict__ bl){
  int t = blockIdx.x*256 + threadIdx.x;
  int base = t*4;
  int w4 = base & 127, h = (base>>7)&127, bc = base>>14;
  int ch = bc & 63;
  const float* src = g_out3 + bc*HW;
  const float* kk = wl + ch*9;
  float bv = bl[ch];
  float o0=bv,o1=bv,o2=bv,o3=bv;
#pragma unroll
  for (int dy = 0; dy < 3; dy++){
    int ih = h + dy - 1;
    ih = (ih < 0) ? -ih : ((ih > 127) ? 254-ih : ih);
    const float* r = src + ih*128 + w4;
    float4 m = *(const float4*)r;
    float lf = (w4 > 0)   ? r[-1] : r[1];
    float rt = (w4 < 124) ? r[4]  : r[2];
    float ka = kk[dy*3], kb = kk[dy*3+1], kc = kk[dy*3+2];
    o0 = fmaf(lf,ka,fmaf(m.x,kb,fmaf(m.y,kc,o0)));
    o1 = fmaf(m.x,ka,fmaf(m.y,kb,fmaf(m.z,kc,o1)));
    o2 = fmaf(m.y,ka,fmaf(m.z,kb,fmaf(m.w,kc,o2)));
    o3 = fmaf(m.z,ka,fmaf(m.w,kb,fmaf(rt,kc,o3)));
  }
  *(float4*)(g_lp + base) = make_float4(o0,o1,o2,o3);
}

// ---------------- bilinear x2 upsample, align_corners, 4 px/thread ----------------
__global__ __launch_bounds__(256) void k_up(float* __restrict__ outp){
  int t = blockIdx.x*256 + threadIdx.x;
  int ix = t*4;
  int X = ix & 255, Y = (ix>>8)&255, bc = ix>>16;
  float cy = Y * (127.0f/255.0f);
  int y0 = (int)cy; if (y0 > 126) y0 = 126;
  float wy = cy - (float)y0;
  const float* tr = g_lp + bc*HW + y0*128;
  float4 res;
#pragma unroll
  for (int i = 0; i < 4; i++){
    float cx = (X+i) * (127.0f/255.0f);
    int x0 = (int)cx; if (x0 > 126) x0 = 126;
    float wx = cx - (float)x0;
    float v00 = tr[x0],       v01 = tr[x0+1];
    float v10 = tr[128+x0],   v11 = tr[128+x0+1];
    float u0 = v00 + (v10 - v00)*wy;
    float u1 = v01 + (v11 - v01)*wy;
    ((float*)&res)[i] = u0 + (u1 - u0)*wx;
  }
  *(float4*)(outp + ix) = res;
}

// ---------------- launch ----------------
extern "C" void kernel_launch(void* const* d_in, const int* in_sizes, int n_in,
                              void* d_out, int out_size){
  const float* x     = (const float*)d_in[0];
  const float* qkvw  = (const float*)d_in[1];
  const float* lcew  = (const float*)d_in[2];
  const float* gatew = (const float*)d_in[3];
  const float* gateb = (const float*)d_in[4];
  const float* temp  = (const float*)d_in[5];
  const float* relh  = (const float*)d_in[6];
  const float* relw  = (const float*)d_in[7];
  const float* downw = (const float*)d_in[8];
  const float* downb = (const float*)d_in[9];
  const float* upw   = (const float*)d_in[10];
  const float* upb   = (const float*)d_in[11];
  const float* gatingw = (const float*)d_in[12];
  const float* gatingb = (const float*)d_in[13];
  const float* projw = (const float*)d_in[14];
  const float* lpw   = (const float*)d_in[15];
  const float* lpb   = (const float*)d_in[16];
  float* outp = (float*)d_out;

  k_pool_qkv<<<512, 256>>>(x, qkvw);
  k_dw3<<<(BATCH*C3*HW)/1024, 256>>>(lcew);
  k_gram<<<dim3(128, BATCH), 256>>>();
  k_reduce<<<1024, 256>>>();
  k_stats<<<BATCH, 256>>>();
  k_attn<<<dim3(256, NHEADS, BATCH), 64>>>(gatew, gateb, temp, relh, relw);
  k_mlp<<<512, 256>>>(gatingw, gatingb, downw, downb, upw, upb, projw);
  k_lp<<<(BATCH*NCH*HW)/1024, 256>>>(lpw, lpb);
  k_up<<<(BATCH*NCH*65536)/1024, 256>>>(outp);
}